// round 12
// baseline (speedup 1.0000x reference)
#include <cuda_runtime.h>
#include <cuda_bf16.h>
#include <cuda_fp16.h>
#include <cstdint>

#define BSZ 2
#define SEQLEN 2048
#define NHEADS 32
#define HDIM 128
#define DIM 4096
#define NTOK (BSZ * SEQLEN)              // 4096
#define OUT_ELEMS ((size_t)NTOK * DIM)   // 16,777,216
#define WSZ ((size_t)DIM * DIM)

// ---------------- GEMM tiling: 256x128 CTA tile, BK=32, 1-term fp16 ---------
#define BK 32
#define CHUNKS (DIM / BK)                // 128
#define A_TILE_B 16384                   // 256 rows x 64 B
#define B_TILE_B 8192                    // 128 rows x 64 B
#define STAGE_B (A_TILE_B + B_TILE_B)    // 24576
#define NSTAGE 8
#define GEMM_SMEM (NSTAGE * STAGE_B + 64)       // 196672 B

// ---------------- attention tiling: 1-term fp16 ----------------
#define AQ_STRIDE 272                    // bytes per Q/K smem row (136 halves)
#define AV_STRIDE 144                    // bytes per Vt smem row (72 halves)
#define Q_BYTES (128 * AQ_STRIDE)        // 34816
#define K_BYTES (64 * AQ_STRIDE)         // 17408
#define VT_BYTES (128 * AV_STRIDE)       // 18432
#define KVBUF_BYTES (K_BYTES + VT_BYTES)           // 35840
#define ATTN_SMEM (Q_BYTES + 2 * KVBUF_BYTES)      // 106496

// ---------------- scratch (device globals; no allocation allowed) -----------
__device__ __align__(256) __half g_xh[OUT_ELEMS];       // x fp16 (A layout)
__device__ __align__(256) __half g_wh[4ull * WSZ];      // weights fp16 (B layout)
__device__ __align__(256) __half g_ah[OUT_ELEMS];       // attn out fp16 (A layout)
__device__ __align__(256) __half g_q16[OUT_ELEMS];      // rotated Q fp16 [B,H,S,D]
__device__ __align__(256) __half g_k16[OUT_ELEMS];      // rotated K fp16 [B,H,S,D]
__device__ __align__(256) __half g_vt16[OUT_ELEMS];     // V^T fp16 [B,H,D,S]

// ---------------- PTX helpers ------------------------------------------------
__device__ __forceinline__ uint32_t smem_u32(const void* p) {
    uint32_t a;
    asm("{ .reg .u64 t; cvta.to.shared.u64 t, %1; cvt.u32.u64 %0, t; }" : "=r"(a) : "l"(p));
    return a;
}
__device__ __forceinline__ void cp16(uint32_t dst, const void* src) {
    asm volatile("cp.async.cg.shared.global [%0], [%1], 16;" :: "r"(dst), "l"(src));
}
__device__ __forceinline__ void bulk_cp(uint32_t dst, const void* src, uint32_t bytes,
                                        uint32_t mbar) {
    asm volatile(
        "cp.async.bulk.shared::cta.global.mbarrier::complete_tx::bytes [%0], [%1], %2, [%3];"
        :: "r"(dst), "l"(src), "r"(bytes), "r"(mbar) : "memory");
}
__device__ __forceinline__ void mbar_expect(uint32_t mbar, uint32_t bytes) {
    asm volatile("mbarrier.arrive.expect_tx.shared.b64 _, [%0], %1;"
                 :: "r"(mbar), "r"(bytes) : "memory");
}
__device__ __forceinline__ void mbar_wait(uint32_t mbar, uint32_t parity) {
    asm volatile(
        "{\n\t.reg .pred P;\n\t"
        "LAB%=:\n\t"
        "mbarrier.try_wait.parity.acquire.cta.shared::cta.b64 P, [%0], %1, 0x989680;\n\t"
        "@!P bra LAB%=;\n\t}"
        :: "r"(mbar), "r"(parity) : "memory");
}
__device__ __forceinline__ void ldsm4(uint32_t* r, uint32_t addr) {
    asm volatile("ldmatrix.sync.aligned.m8n8.x4.shared.b16 {%0,%1,%2,%3}, [%4];"
        : "=r"(r[0]), "=r"(r[1]), "=r"(r[2]), "=r"(r[3]) : "r"(addr));
}
__device__ __forceinline__ void mma_f16(float* c, const uint32_t* a, const uint32_t* b) {
    asm volatile("mma.sync.aligned.m16n8k16.row.col.f32.f16.f16.f32 "
        "{%0,%1,%2,%3}, {%4,%5,%6,%7}, {%8,%9}, {%0,%1,%2,%3};"
        : "+f"(c[0]), "+f"(c[1]), "+f"(c[2]), "+f"(c[3])
        : "r"(a[0]), "r"(a[1]), "r"(a[2]), "r"(a[3]), "r"(b[0]), "r"(b[1]));
}

// ---------------------------------------------------------------------------
// Combined conversion: blockIdx.y = 0 -> x into A layout (256-row tiles);
// 1..4 -> wq/wk/wv/wo into B layout (128-row tiles).
// ---------------------------------------------------------------------------
__global__ __launch_bounds__(256) void convert_all(
        const float* __restrict__ x,
        const float* __restrict__ w0, const float* __restrict__ w1,
        const float* __restrict__ w2, const float* __restrict__ w3,
        __half* __restrict__ xh, __half* __restrict__ wh) {
    int m = blockIdx.y;
    const float* src = (m == 0) ? x : (m == 1) ? w0 : (m == 2) ? w1 : (m == 3) ? w2 : w3;

    int idx = blockIdx.x * 256 + threadIdx.x;
    int r = idx >> 9;
    int k = (idx & 511) << 3;
    const float4* s = (const float4*)(src + ((size_t)r << 12) + k);
    float4 v0 = s[0], v1 = s[1];
    float f[8] = {v0.x, v0.y, v0.z, v0.w, v1.x, v1.y, v1.z, v1.w};
    __half h8[8];
#pragma unroll
    for (int j = 0; j < 8; j++) h8[j] = __float2half_rn(f[j]);
    int ck = k >> 5, c16 = (k & 31) >> 3;
    if (m == 0) {
        int mt = r >> 8, rr = r & 255;
        size_t off = ((((size_t)(mt * 128 + ck)) * 256 + rr) << 6) +
                     ((c16 ^ ((rr >> 1) & 3)) << 4);
        *(uint4*)((char*)xh + off) = *(uint4*)h8;
    } else {
        __half* hi = wh + (size_t)(m - 1) * WSZ;
        int nt = r >> 7, rr = r & 127;
        size_t off = ((((size_t)(nt * 128 + ck)) * 128 + rr) << 6) +
                     ((c16 ^ ((rr >> 1) & 3)) << 4);
        *(uint4*)((char*)hi + off) = *(uint4*)h8;
    }
}

// ---------------- shared GEMM machinery (macros used by both kernels) -------
#define GEMM_PROLOG()                                                             \
    extern __shared__ char sm_raw[];                                              \
    const uint32_t base = smem_u32(sm_raw);                                       \
    const uint32_t mb = base + NSTAGE * STAGE_B;                                  \
    const int tid = threadIdx.x;                                                  \
    const int warp = tid >> 5, lane = tid & 31;                                   \
    const int wm = warp & 3, wn = warp >> 2;                                      \
    const int nt = blockIdx.x, mt = blockIdx.y;                                   \
    const size_t mtC = (size_t)mt * CHUNKS;                                       \
    const size_t ntC = (size_t)nt * CHUNKS;                                       \
    if (tid == 0) {                                                               \
        _Pragma("unroll")                                                         \
        for (int s = 0; s < NSTAGE; s++)                                          \
            asm volatile("mbarrier.init.shared.b64 [%0], %1;"                     \
                         :: "r"(mb + 8 * s), "r"(1u) : "memory");                 \
        asm volatile("fence.proxy.async.shared::cta;" ::: "memory");              \
    }                                                                             \
    __syncthreads();

#define ISSUE(c, s)                                                               \
    do {                                                                          \
        if (tid == 0) {                                                           \
            uint32_t mb_ = mb + 8 * (s);                                          \
            mbar_expect(mb_, STAGE_B);                                            \
            uint32_t st_ = base + (s) * STAGE_B;                                  \
            bulk_cp(st_, (const char*)Ah + (mtC + (c)) * A_TILE_B, A_TILE_B, mb_); \
            bulk_cp(st_ + A_TILE_B, (const char*)Bh + (ntC + (c)) * B_TILE_B, B_TILE_B, mb_); \
        }                                                                         \
    } while (0)

#define GEMM_MAINLOOP()                                                           \
    _Pragma("unroll")                                                             \
    for (int p = 0; p < NSTAGE - 1; p++) ISSUE(p, p);                             \
    const int rowA = wm * 64 + (lane & 15);                                       \
    const int xa = (rowA >> 1) & 3;                                               \
    const int lsA = lane >> 4;                                                    \
    const uint32_t cA0 = (uint32_t)((lsA ^ xa) << 4);                             \
    const uint32_t cA1 = (uint32_t)(((2 | lsA) ^ xa) << 4);                       \
    const uint32_t aRow = (uint32_t)rowA * 64;                                    \
    const int rowB = wn * 64 + (lane & 7) + ((lane & 16) >> 1);                   \
    const int xb = (rowB >> 1) & 3;                                               \
    const int lsB = (lane & 8) >> 3;                                              \
    const uint32_t cB0 = (uint32_t)((lsB ^ xb) << 4);                             \
    const uint32_t cB1 = (uint32_t)(((2 | lsB) ^ xb) << 4);                       \
    const uint32_t bRow = (uint32_t)rowB * 64;                                    \
    float c[4][8][4];                                                             \
    _Pragma("unroll")                                                             \
    for (int mi = 0; mi < 4; mi++)                                                \
        _Pragma("unroll")                                                         \
        for (int ni = 0; ni < 8; ni++)                                            \
            _Pragma("unroll")                                                     \
            for (int j = 0; j < 4; j++) c[mi][ni][j] = 0.f;                       \
    for (int ck = 0; ck < CHUNKS; ck++) {                                         \
        const int s = ck & 7;                                                     \
        mbar_wait(mb + 8 * s, (ck >> 3) & 1);                                     \
        const uint32_t sb = base + s * STAGE_B;                                   \
        const uint32_t aHi = sb + aRow;                                           \
        const uint32_t bHi = sb + A_TILE_B + bRow;                                \
        _Pragma("unroll")                                                         \
        for (int kk = 0; kk < 2; kk++) {                                          \
            const uint32_t ca = kk ? cA1 : cA0;                                   \
            const uint32_t cb = kk ? cB1 : cB0;                                   \
            uint32_t bh[16];                                                      \
            _Pragma("unroll")                                                     \
            for (int g = 0; g < 4; g++) ldsm4(bh + g * 4, bHi + g * 1024 + cb);   \
            _Pragma("unroll")                                                     \
            for (int mi = 0; mi < 4; mi++) {                                      \
                uint32_t ah[4];                                                   \
                ldsm4(ah, aHi + mi * 1024 + ca);                                  \
                _Pragma("unroll")                                                 \
                for (int ni = 0; ni < 8; ni++)                                    \
                    mma_f16(c[mi][ni], ah, &bh[ni * 2]);                          \
            }                                                                     \
        }                                                                         \
        __syncthreads();                                                          \
        if (ck + NSTAGE - 1 < CHUNKS) ISSUE(ck + NSTAGE - 1, (ck + NSTAGE - 1) & 7); \
    }

// ---------------------------------------------------------------------------
// QKV GEMM with fused rotary epilogue.
// nt 0..31 -> Q (rotary + scale -> fp16 q16 [B,H,S,D])
// nt 32..63 -> K (rotary -> fp32 Kh [token][4096] + fp16 k16 [B,H,S,D])
// nt 64..95 -> V (fp32 Vh [token][4096])
// ---------------------------------------------------------------------------
__global__ __launch_bounds__(256)
void gemm_qkv(const __half* __restrict__ Ah, const __half* __restrict__ Bh,
              const float* __restrict__ fc,
              float* __restrict__ Kh, float* __restrict__ Vh,
              __half* __restrict__ q16, __half* __restrict__ k16) {
    GEMM_PROLOG()
    GEMM_MAINLOOP()

    const float QSC = 1.44269504088896f / 11.3137084989848f;  // log2e / sqrt(128)
    const int m = nt >> 5;
    const int cr = lane >> 2, cc = (lane & 3) * 2;
    const int rowbase = mt * 256 + wm * 64 + cr;
    const int dbase = (nt & 31) * 128 + wn * 64 + cc;

    if (m == 2) {
        float* Cw = Vh + (size_t)rowbase * DIM + dbase;
#pragma unroll
        for (int mi = 0; mi < 4; mi++)
#pragma unroll
            for (int ni = 0; ni < 8; ni++) {
                float* p0 = Cw + (size_t)(mi * 16) * DIM + ni * 8;
                *(float2*)p0 = make_float2(c[mi][ni][0], c[mi][ni][1]);
                *(float2*)(p0 + 8 * DIM) = make_float2(c[mi][ni][2], c[mi][ni][3]);
            }
    } else {
#pragma unroll
        for (int mi = 0; mi < 4; mi++) {
#pragma unroll
            for (int ni = 0; ni < 8; ni++) {
                int d = dbase + ni * 8;
                int h = d >> 7, dd = d & 127, p = dd >> 1;
#pragma unroll
                for (int h2 = 0; h2 < 2; h2++) {
                    int token = rowbase + mi * 16 + h2 * 8;
                    int b = token >> 11, s = token & (SEQLEN - 1);
                    float2 cs = *(const float2*)(fc + ((size_t)s * 64 + p) * 2);
                    float v0 = c[mi][ni][h2 * 2], v1 = c[mi][ni][h2 * 2 + 1];
                    float rx = v0 * cs.x - v1 * cs.y;
                    float ry = v0 * cs.y + v1 * cs.x;
                    size_t o16 = ((((size_t)(b * NHEADS + h)) * SEQLEN + s) << 7) + dd;
                    if (m == 0) {
                        __half2 hv = __floats2half2_rn(rx * QSC, ry * QSC);
                        *(uint32_t*)(q16 + o16) = *(uint32_t*)&hv;
                    } else {
                        *(float2*)(Kh + (size_t)token * DIM + d) = make_float2(rx, ry);
                        __half2 hv = __floats2half2_rn(rx, ry);
                        *(uint32_t*)(k16 + o16) = *(uint32_t*)&hv;
                    }
                }
            }
        }
    }
}

// ---------------------------------------------------------------------------
// Plain fp16 GEMM (Wo projection), fp32 output.
// ---------------------------------------------------------------------------
__global__ __launch_bounds__(256)
void gemm_f16(const __half* __restrict__ Ah, const __half* __restrict__ Bh,
              float* __restrict__ C0) {
    GEMM_PROLOG()
    GEMM_MAINLOOP()

    float* Cw = C0 + (size_t)(mt * 256 + wm * 64) * DIM + nt * 128 + wn * 64;
    const int cr = lane >> 2, cc = (lane & 3) * 2;
#pragma unroll
    for (int mi = 0; mi < 4; mi++)
#pragma unroll
        for (int ni = 0; ni < 8; ni++) {
            float* p0 = Cw + (size_t)(mi * 16 + cr) * DIM + ni * 8 + cc;
            *(float2*)p0 = make_float2(c[mi][ni][0], c[mi][ni][1]);
            *(float2*)(p0 + 8 * DIM) = make_float2(c[mi][ni][2], c[mi][ni][3]);
        }
}

// ---------------------------------------------------------------------------
// V transpose: fp32 [B,S,H,D] -> fp16 [B,H,D,S]
// ---------------------------------------------------------------------------
__global__ __launch_bounds__(256) void v_transpose(const float* __restrict__ V,
                                                   __half* __restrict__ vt16) {
    __shared__ float t[32][33];
    int s0 = blockIdx.x * 32, d0 = blockIdx.y * 32;
    int bh = blockIdx.z;
    int b = bh >> 5, h = bh & 31;
#pragma unroll
    for (int i = 0; i < 4; i++) {
        int s = s0 + threadIdx.y + i * 8;
        t[threadIdx.y + i * 8][threadIdx.x] =
            V[(((size_t)(b * SEQLEN + s) * NHEADS) + h) * HDIM + d0 + threadIdx.x];
    }
    __syncthreads();
#pragma unroll
    for (int i = 0; i < 4; i++) {
        int d = d0 + threadIdx.y + i * 8;
        float v = t[threadIdx.x][threadIdx.y + i * 8];
        size_t o = ((size_t)bh * HDIM + d) * SEQLEN + s0 + threadIdx.x;
        vt16[o] = __float2half_rn(v);
    }
}

// ---------------------------------------------------------------------------
// Flash attention, 1-term fp16 mma.sync (unchanged from round 11).
// ---------------------------------------------------------------------------
__global__ __launch_bounds__(256)
void flash_attn(const __half* __restrict__ Q16,
                const __half* __restrict__ K16,
                const __half* __restrict__ Vt16,
                __half* __restrict__ Oh) {
    extern __shared__ char sm_raw[];
    const uint32_t base = smem_u32(sm_raw);
    const int tid = threadIdx.x, warp = tid >> 5, lane = tid & 31;
    const int qt = blockIdx.x, h = blockIdx.y, b = blockIdx.z;
    const size_t bhd = (size_t)(b * NHEADS + h);

    const uint32_t sQ = base;
    const uint32_t sKV = base + Q_BYTES;

    {
        const char* gq = (const char*)(Q16 + (bhd * SEQLEN + qt * 128) * HDIM);
        int row = tid >> 4, ch = tid & 15;
#pragma unroll
        for (int i = 0; i < 8; i++) {
            int r = row + i * 16;
            cp16(sQ + r * AQ_STRIDE + ch * 16, gq + r * 256 + ch * 16);
        }
    }

#define LOADKV(kb_, p_)                                                              \
    do {                                                                             \
        uint32_t kvb_ = sKV + (p_) * KVBUF_BYTES;                                    \
        const char* gk_ = (const char*)(K16 + (bhd * SEQLEN + (kb_) * 64) * HDIM);   \
        {                                                                            \
            int row_ = tid >> 4, ch_ = tid & 15;                                     \
            _Pragma("unroll")                                                        \
            for (int i_ = 0; i_ < 4; i_++) {                                         \
                int r_ = row_ + i_ * 16;                                             \
                cp16(kvb_ + r_ * AQ_STRIDE + ch_ * 16, gk_ + r_ * 256 + ch_ * 16);   \
            }                                                                        \
        }                                                                            \
        const char* gv_ = (const char*)(Vt16 + bhd * HDIM * SEQLEN + (kb_) * 64);    \
        {                                                                            \
            int row_ = tid >> 3, ch_ = tid & 7;                                      \
            _Pragma("unroll")                                                        \
            for (int i_ = 0; i_ < 4; i_++) {                                         \
                int r_ = row_ + i_ * 32;                                             \
                cp16(kvb_ + K_BYTES + r_ * AV_STRIDE + ch_ * 16,                     \
                     gv_ + (size_t)r_ * SEQLEN * 2 + ch_ * 16);                      \
            }                                                                        \
        }                                                                            \
        asm volatile("cp.async.commit_group;" ::: "memory");                         \
    } while (0)

    const int nt = 2 * qt + 2;
    LOADKV(0, 0);
    LOADKV(1, 1);

    const uint32_t aQoff = (warp * 16 + (lane & 15)) * AQ_STRIDE + ((lane >> 4) << 4);
    const uint32_t bKoff = ((lane & 7) + ((lane & 16) >> 1)) * AQ_STRIDE + (lane & 8) * 2;
    const uint32_t bVoff = ((lane & 7) + ((lane & 16) >> 1)) * AV_STRIDE + (lane & 8) * 2;

    float o[16][4];
#pragma unroll
    for (int j = 0; j < 16; j++)
#pragma unroll
        for (int c = 0; c < 4; c++) o[j][c] = 0.f;
    float m_run[2] = {-1e30f, -1e30f}, l_run[2] = {0.f, 0.f};

    for (int kb = 0; kb < nt; kb++) {
        const uint32_t kvb = sKV + (kb & 1) * KVBUF_BYTES;
        if (kb + 1 < nt) asm volatile("cp.async.wait_group 1;" ::: "memory");
        else             asm volatile("cp.async.wait_group 0;" ::: "memory");
        __syncthreads();

        float s[8][4];
#pragma unroll
        for (int j = 0; j < 8; j++)
#pragma unroll
            for (int c = 0; c < 4; c++) s[j][c] = 0.f;

#pragma unroll
        for (int ks = 0; ks < 8; ks++) {
            uint32_t ah[4];
            ldsm4(ah, sQ + aQoff + ks * 32);
#pragma unroll
            for (int nb = 0; nb < 4; nb++) {
                uint32_t kh4[4];
                ldsm4(kh4, kvb + bKoff + nb * 16 * AQ_STRIDE + ks * 32);
                mma_f16(s[nb * 2], ah, kh4);
                mma_f16(s[nb * 2 + 1], ah, kh4 + 2);
            }
        }

        if (kb >= 2 * qt) {
            int r0 = qt * 128 + warp * 16 + (lane >> 2);
            int c0 = kb * 64 + (lane & 3) * 2;
#pragma unroll
            for (int j = 0; j < 8; j++)
#pragma unroll
                for (int c = 0; c < 4; c++) {
                    int col = c0 + j * 8 + (c & 1);
                    int row = r0 + ((c & 2) ? 8 : 0);
                    if (col > row) s[j][c] = -1e30f;
                }
        }

        float mloc[2] = {-1e30f, -1e30f};
#pragma unroll
        for (int j = 0; j < 8; j++) {
            mloc[0] = fmaxf(mloc[0], fmaxf(s[j][0], s[j][1]));
            mloc[1] = fmaxf(mloc[1], fmaxf(s[j][2], s[j][3]));
        }
        float mnew[2], alpha[2], rs[2];
#pragma unroll
        for (int h2 = 0; h2 < 2; h2++) {
            mloc[h2] = fmaxf(mloc[h2], __shfl_xor_sync(0xffffffffu, mloc[h2], 1));
            mloc[h2] = fmaxf(mloc[h2], __shfl_xor_sync(0xffffffffu, mloc[h2], 2));
            mnew[h2] = fmaxf(m_run[h2], mloc[h2]);
            alpha[h2] = exp2f(m_run[h2] - mnew[h2]);
            rs[h2] = 0.f;
        }
#pragma unroll
        for (int j = 0; j < 8; j++) {
            s[j][0] = exp2f(s[j][0] - mnew[0]);
            s[j][1] = exp2f(s[j][1] - mnew[0]);
            s[j][2] = exp2f(s[j][2] - mnew[1]);
            s[j][3] = exp2f(s[j][3] - mnew[1]);
            rs[0] += s[j][0] + s[j][1];
            rs[1] += s[j][2] + s[j][3];
        }
#pragma unroll
        for (int h2 = 0; h2 < 2; h2++) {
            rs[h2] += __shfl_xor_sync(0xffffffffu, rs[h2], 1);
            rs[h2] += __shfl_xor_sync(0xffffffffu, rs[h2], 2);
            l_run[h2] = l_run[h2] * alpha[h2] + rs[h2];
            m_run[h2] = mnew[h2];
        }
#pragma unroll
        for (int j = 0; j < 16; j++) {
            o[j][0] *= alpha[0];
            o[j][1] *= alpha[0];
            o[j][2] *= alpha[1];
            o[j][3] *= alpha[1];
        }

#pragma unroll
        for (int kc = 0; kc < 4; kc++) {
            uint32_t pa[4];
            __half2 p0 = __floats2half2_rn(s[2 * kc][0], s[2 * kc][1]);
            __half2 p1 = __floats2half2_rn(s[2 * kc][2], s[2 * kc][3]);
            __half2 p2 = __floats2half2_rn(s[2 * kc + 1][0], s[2 * kc + 1][1]);
            __half2 p3 = __floats2half2_rn(s[2 * kc + 1][2], s[2 * kc + 1][3]);
            pa[0] = *(uint32_t*)&p0;
            pa[1] = *(uint32_t*)&p1;
            pa[2] = *(uint32_t*)&p2;
            pa[3] = *(uint32_t*)&p3;
#pragma unroll
            for (int nb = 0; nb < 8; nb++) {
                uint32_t vh4[4];
                ldsm4(vh4, kvb + K_BYTES + bVoff + nb * 16 * AV_STRIDE + kc * 32);
                mma_f16(o[nb * 2], pa, vh4);
                mma_f16(o[nb * 2 + 1], pa, vh4 + 2);
            }
        }

        if (kb + 2 < nt) {
            __syncthreads();
            LOADKV(kb + 2, kb & 1);
        }
    }

    // normalize + write fp16 in 256-row tiled-A layout for Wo GEMM
    float inv[2] = {1.f / l_run[0], 1.f / l_run[1]};
    int trow = b * SEQLEN + qt * 128 + warp * 16 + (lane >> 2);
#pragma unroll
    for (int j = 0; j < 16; j++) {
        int c0 = j * 8 + (lane & 3) * 2;
        int k = h * HDIM + c0;
        int ck = k >> 5, c16 = (k & 31) >> 3, bo = (k & 7) * 2;
#pragma unroll
        for (int h2 = 0; h2 < 2; h2++) {
            int t = trow + h2 * 8;
            int mtA = t >> 8, rr = t & 255;
            size_t off = ((((size_t)(mtA * 128 + ck)) * 256 + rr) << 6) +
                         ((c16 ^ ((rr >> 1) & 3)) << 4) + bo;
            __half2 hv = __floats2half2_rn(o[j][h2 * 2] * inv[h2],
                                           o[j][h2 * 2 + 1] * inv[h2]);
            *(uint32_t*)((char*)Oh + off) = *(uint32_t*)&hv;
        }
    }
}

// ---------------------------------------------------------------------------
extern "C" void kernel_launch(void* const* d_in, const int* in_sizes, int n_in,
                              void* d_out, int out_size) {
    const float* x  = (const float*)d_in[0];
    const float* fc = (const float*)d_in[1];
    const float* wq = (const float*)d_in[4];
    const float* wk = (const float*)d_in[5];
    const float* wv = (const float*)d_in[6];
    const float* wo = (const float*)d_in[7];

    float* out = (float*)d_out;
    float* Kh = out + OUT_ELEMS;
    float* Vh = Kh + OUT_ELEMS;

    __half *xh, *wh, *ah, *q16, *k16, *vt16;
    cudaGetSymbolAddress((void**)&xh, g_xh);
    cudaGetSymbolAddress((void**)&wh, g_wh);
    cudaGetSymbolAddress((void**)&ah, g_ah);
    cudaGetSymbolAddress((void**)&q16, g_q16);
    cudaGetSymbolAddress((void**)&k16, g_k16);
    cudaGetSymbolAddress((void**)&vt16, g_vt16);

    const int cblocks = (int)(WSZ / 8 / 256);   // 8 elems per thread

    convert_all<<<dim3(cblocks, 5), 256>>>(x, wq, wk, wv, wo, xh, wh);

    cudaFuncSetAttribute(gemm_qkv, cudaFuncAttributeMaxDynamicSharedMemorySize, GEMM_SMEM);
    cudaFuncSetAttribute(gemm_f16, cudaFuncAttributeMaxDynamicSharedMemorySize, GEMM_SMEM);

    // Fused QKV projection + rotary epilogue
    gemm_qkv<<<dim3(96, NTOK / 256), 256, GEMM_SMEM>>>(xh, wh, fc, Kh, Vh, q16, k16);

    v_transpose<<<dim3(SEQLEN / 32, HDIM / 32, BSZ * NHEADS), dim3(32, 8)>>>(Vh, vt16);

    cudaFuncSetAttribute(flash_attn, cudaFuncAttributeMaxDynamicSharedMemorySize, ATTN_SMEM);
    flash_attn<<<dim3(SEQLEN / 128, NHEADS, BSZ), 256, ATTN_SMEM>>>(q16, k16, vt16, ah);

    // Output projection
    gemm_f16<<<dim3(32, NTOK / 256), 256, GEMM_SMEM>>>(ah, wh + 3 * WSZ, out);
}

// round 13
// speedup vs baseline: 1.0203x; 1.0203x over previous
#include <cuda_runtime.h>
#include <cuda_bf16.h>
#include <cuda_fp16.h>
#include <cstdint>

#define BSZ 2
#define SEQLEN 2048
#define NHEADS 32
#define HDIM 128
#define DIM 4096
#define NTOK (BSZ * SEQLEN)              // 4096
#define OUT_ELEMS ((size_t)NTOK * DIM)   // 16,777,216
#define WSZ ((size_t)DIM * DIM)

// ---------------- GEMM tiling: 256x128 CTA tile, BK=32, 1-term fp16 ---------
#define BK 32
#define CHUNKS (DIM / BK)                // 128
#define A_TILE_B 16384                   // 256 rows x 64 B
#define B_TILE_B 8192                    // 128 rows x 64 B
#define STAGE_B (A_TILE_B + B_TILE_B)    // 24576
#define NSTAGE 8
#define GEMM_SMEM (NSTAGE * STAGE_B + 64)       // 196672 B

// ---------------- attention tiling: 1-term fp16, 2 CTAs/SM ----------------
#define AQ_STRIDE 272                    // bytes per Q/K smem row (136 halves)
#define AV_STRIDE 144                    // bytes per Vt smem row (72 halves)
#define Q_BYTES (128 * AQ_STRIDE)        // 34816
#define K_BYTES (64 * AQ_STRIDE)         // 17408
#define VT_BYTES (128 * AV_STRIDE)       // 18432
#define KVBUF_BYTES (K_BYTES + VT_BYTES)           // 35840
#define ATTN_SMEM (Q_BYTES + 2 * KVBUF_BYTES)      // 106496 (x2 CTAs = 212992)

// ---------------- scratch (device globals; no allocation allowed) -----------
__device__ __align__(256) float g_Q[OUT_ELEMS];
__device__ __align__(256) __half g_xh[OUT_ELEMS];       // x fp16 (A layout)
__device__ __align__(256) __half g_wh[4ull * WSZ];      // weights fp16 (B layout)
__device__ __align__(256) __half g_ah[OUT_ELEMS];       // attn out fp16 (A layout)
__device__ __align__(256) __half g_q16[OUT_ELEMS];      // rotated Q fp16 [B,H,S,D]
__device__ __align__(256) __half g_k16[OUT_ELEMS];      // rotated K fp16 [B,H,S,D]
__device__ __align__(256) __half g_vt16[OUT_ELEMS];     // V^T fp16 [B,H,D,S]

// ---------------- PTX helpers ------------------------------------------------
__device__ __forceinline__ uint32_t smem_u32(const void* p) {
    uint32_t a;
    asm("{ .reg .u64 t; cvta.to.shared.u64 t, %1; cvt.u32.u64 %0, t; }" : "=r"(a) : "l"(p));
    return a;
}
__device__ __forceinline__ void cp16(uint32_t dst, const void* src) {
    asm volatile("cp.async.cg.shared.global [%0], [%1], 16;" :: "r"(dst), "l"(src));
}
__device__ __forceinline__ void bulk_cp(uint32_t dst, const void* src, uint32_t bytes,
                                        uint32_t mbar) {
    asm volatile(
        "cp.async.bulk.shared::cta.global.mbarrier::complete_tx::bytes [%0], [%1], %2, [%3];"
        :: "r"(dst), "l"(src), "r"(bytes), "r"(mbar) : "memory");
}
__device__ __forceinline__ void mbar_expect(uint32_t mbar, uint32_t bytes) {
    asm volatile("mbarrier.arrive.expect_tx.shared.b64 _, [%0], %1;"
                 :: "r"(mbar), "r"(bytes) : "memory");
}
__device__ __forceinline__ void mbar_wait(uint32_t mbar, uint32_t parity) {
    asm volatile(
        "{\n\t.reg .pred P;\n\t"
        "LAB%=:\n\t"
        "mbarrier.try_wait.parity.acquire.cta.shared::cta.b64 P, [%0], %1, 0x989680;\n\t"
        "@!P bra LAB%=;\n\t}"
        :: "r"(mbar), "r"(parity) : "memory");
}
__device__ __forceinline__ void ldsm4(uint32_t* r, uint32_t addr) {
    asm volatile("ldmatrix.sync.aligned.m8n8.x4.shared.b16 {%0,%1,%2,%3}, [%4];"
        : "=r"(r[0]), "=r"(r[1]), "=r"(r[2]), "=r"(r[3]) : "r"(addr));
}
__device__ __forceinline__ void mma_f16(float* c, const uint32_t* a, const uint32_t* b) {
    asm volatile("mma.sync.aligned.m16n8k16.row.col.f32.f16.f16.f32 "
        "{%0,%1,%2,%3}, {%4,%5,%6,%7}, {%8,%9}, {%0,%1,%2,%3};"
        : "+f"(c[0]), "+f"(c[1]), "+f"(c[2]), "+f"(c[3])
        : "r"(a[0]), "r"(a[1]), "r"(a[2]), "r"(a[3]), "r"(b[0]), "r"(b[1]));
}

// ---------------------------------------------------------------------------
// Combined conversion: blockIdx.y = 0 -> x into A layout (256-row tiles);
// 1..4 -> wq/wk/wv/wo into B layout (128-row tiles).
// ---------------------------------------------------------------------------
__global__ __launch_bounds__(256) void convert_all(
        const float* __restrict__ x,
        const float* __restrict__ w0, const float* __restrict__ w1,
        const float* __restrict__ w2, const float* __restrict__ w3,
        __half* __restrict__ xh, __half* __restrict__ wh) {
    int m = blockIdx.y;
    const float* src = (m == 0) ? x : (m == 1) ? w0 : (m == 2) ? w1 : (m == 3) ? w2 : w3;

    int idx = blockIdx.x * 256 + threadIdx.x;
    int r = idx >> 9;
    int k = (idx & 511) << 3;
    const float4* s = (const float4*)(src + ((size_t)r << 12) + k);
    float4 v0 = s[0], v1 = s[1];
    float f[8] = {v0.x, v0.y, v0.z, v0.w, v1.x, v1.y, v1.z, v1.w};
    __half h8[8];
#pragma unroll
    for (int j = 0; j < 8; j++) h8[j] = __float2half_rn(f[j]);
    int ck = k >> 5, c16 = (k & 31) >> 3;
    if (m == 0) {
        int mt = r >> 8, rr = r & 255;
        size_t off = ((((size_t)(mt * 128 + ck)) * 256 + rr) << 6) +
                     ((c16 ^ ((rr >> 1) & 3)) << 4);
        *(uint4*)((char*)xh + off) = *(uint4*)h8;
    } else {
        __half* hi = wh + (size_t)(m - 1) * WSZ;
        int nt = r >> 7, rr = r & 127;
        size_t off = ((((size_t)(nt * 128 + ck)) * 128 + rr) << 6) +
                     ((c16 ^ ((rr >> 1) & 3)) << 4);
        *(uint4*)((char*)hi + off) = *(uint4*)h8;
    }
}

// ---------------------------------------------------------------------------
// fp16 1-term GEMM (as round 10/11). Output routed to C0/C1/C2 by nt>>5.
// ---------------------------------------------------------------------------
__global__ __launch_bounds__(256)
void gemm_f16(const __half* __restrict__ Ah, const __half* __restrict__ Bh,
              float* __restrict__ C0, float* __restrict__ C1, float* __restrict__ C2) {
    extern __shared__ char sm_raw[];
    const uint32_t base = smem_u32(sm_raw);
    const uint32_t mb = base + NSTAGE * STAGE_B;
    const int tid = threadIdx.x;
    const int warp = tid >> 5, lane = tid & 31;
    const int wm = warp & 3, wn = warp >> 2;
    const int nt = blockIdx.x, mt = blockIdx.y;
    const size_t mtC = (size_t)mt * CHUNKS;
    const size_t ntC = (size_t)nt * CHUNKS;

    if (tid == 0) {
#pragma unroll
        for (int s = 0; s < NSTAGE; s++)
            asm volatile("mbarrier.init.shared.b64 [%0], %1;" :: "r"(mb + 8 * s), "r"(1u) : "memory");
        asm volatile("fence.proxy.async.shared::cta;" ::: "memory");
    }
    __syncthreads();

#define ISSUE(c, s)                                                              \
    do {                                                                         \
        if (tid == 0) {                                                          \
            uint32_t mb_ = mb + 8 * (s);                                         \
            mbar_expect(mb_, STAGE_B);                                           \
            uint32_t st_ = base + (s) * STAGE_B;                                 \
            bulk_cp(st_, (const char*)Ah + (mtC + (c)) * A_TILE_B, A_TILE_B, mb_); \
            bulk_cp(st_ + A_TILE_B, (const char*)Bh + (ntC + (c)) * B_TILE_B, B_TILE_B, mb_); \
        }                                                                        \
    } while (0)

#pragma unroll
    for (int p = 0; p < NSTAGE - 1; p++) ISSUE(p, p);

    const int rowA = wm * 64 + (lane & 15);
    const int xa = (rowA >> 1) & 3;
    const int lsA = lane >> 4;
    const uint32_t cA0 = (uint32_t)((lsA ^ xa) << 4);
    const uint32_t cA1 = (uint32_t)(((2 | lsA) ^ xa) << 4);
    const uint32_t aRow = (uint32_t)rowA * 64;

    const int rowB = wn * 64 + (lane & 7) + ((lane & 16) >> 1);
    const int xb = (rowB >> 1) & 3;
    const int lsB = (lane & 8) >> 3;
    const uint32_t cB0 = (uint32_t)((lsB ^ xb) << 4);
    const uint32_t cB1 = (uint32_t)(((2 | lsB) ^ xb) << 4);
    const uint32_t bRow = (uint32_t)rowB * 64;

    float c[4][8][4];
#pragma unroll
    for (int mi = 0; mi < 4; mi++)
#pragma unroll
        for (int ni = 0; ni < 8; ni++)
#pragma unroll
            for (int j = 0; j < 4; j++) c[mi][ni][j] = 0.f;

    for (int ck = 0; ck < CHUNKS; ck++) {
        const int s = ck & 7;
        mbar_wait(mb + 8 * s, (ck >> 3) & 1);

        const uint32_t sb = base + s * STAGE_B;
        const uint32_t aHi = sb + aRow;
        const uint32_t bHi = sb + A_TILE_B + bRow;

#pragma unroll
        for (int kk = 0; kk < 2; kk++) {
            const uint32_t ca = kk ? cA1 : cA0;
            const uint32_t cb = kk ? cB1 : cB0;
            uint32_t bh[16];
#pragma unroll
            for (int g = 0; g < 4; g++) ldsm4(bh + g * 4, bHi + g * 1024 + cb);
#pragma unroll
            for (int mi = 0; mi < 4; mi++) {
                uint32_t ah[4];
                ldsm4(ah, aHi + mi * 1024 + ca);
#pragma unroll
                for (int ni = 0; ni < 8; ni++)
                    mma_f16(c[mi][ni], ah, &bh[ni * 2]);
            }
        }
        __syncthreads();
        if (ck + NSTAGE - 1 < CHUNKS) ISSUE(ck + NSTAGE - 1, (ck + NSTAGE - 1) & 7);
    }

    float* Cb = (nt < 32) ? C0 : (nt < 64) ? C1 : C2;
    float* Cw = Cb + (size_t)(mt * 256 + wm * 64) * DIM + (nt & 31) * 128 + wn * 64;
    const int cr = lane >> 2, cc = (lane & 3) * 2;
#pragma unroll
    for (int mi = 0; mi < 4; mi++)
#pragma unroll
        for (int ni = 0; ni < 8; ni++) {
            float* p0 = Cw + (size_t)(mi * 16 + cr) * DIM + ni * 8 + cc;
            float* p1 = p0 + 8 * DIM;
            *(float2*)p0 = make_float2(c[mi][ni][0], c[mi][ni][1]);
            *(float2*)p1 = make_float2(c[mi][ni][2], c[mi][ni][3]);
        }
}

// ---------------------------------------------------------------------------
// Rotary: Q (scaled by log2e/sqrt(d)) and K -> fp16 [B,H,S,D]; K fp32 in place.
// ---------------------------------------------------------------------------
__global__ __launch_bounds__(256) void rotary_convert(
        const float* __restrict__ Q, float* __restrict__ Kf,
        const float* __restrict__ fc,
        __half* __restrict__ q16, __half* __restrict__ k16) {
    const float QSC = 1.44269504088896f / 11.3137084989848f;
    int idx = blockIdx.x * blockDim.x + threadIdx.x;
    int p = idx & 63;
    int h = (idx >> 6) & 31;
    int s = (idx >> 11) & (SEQLEN - 1);
    int b = idx >> 22;

    float c = fc[(s * 64 + p) * 2];
    float sn = fc[(s * 64 + p) * 2 + 1];

    size_t in = (((size_t)(b * SEQLEN + s) * NHEADS) + h) * HDIM + p * 2;
    size_t out = (((size_t)(b * NHEADS + h) * SEQLEN) + s) * HDIM + p * 2;

    float2 q = *(float2*)(Q + in);
    float2 k = *(float2*)(Kf + in);
    float2 qo = {q.x * c - q.y * sn, q.x * sn + q.y * c};
    float2 ko = {k.x * c - k.y * sn, k.x * sn + k.y * c};
    *(float2*)(Kf + in) = ko;

    __half2 q2 = __floats2half2_rn(qo.x * QSC, qo.y * QSC);
    __half2 k2 = __floats2half2_rn(ko.x, ko.y);
    *(uint32_t*)(q16 + out) = *(uint32_t*)&q2;
    *(uint32_t*)(k16 + out) = *(uint32_t*)&k2;
}

// ---------------------------------------------------------------------------
// V transpose: fp32 [B,S,H,D] -> fp16 [B,H,D,S]
// ---------------------------------------------------------------------------
__global__ __launch_bounds__(256) void v_transpose(const float* __restrict__ V,
                                                   __half* __restrict__ vt16) {
    __shared__ float t[32][33];
    int s0 = blockIdx.x * 32, d0 = blockIdx.y * 32;
    int bh = blockIdx.z;
    int b = bh >> 5, h = bh & 31;
#pragma unroll
    for (int i = 0; i < 4; i++) {
        int s = s0 + threadIdx.y + i * 8;
        t[threadIdx.y + i * 8][threadIdx.x] =
            V[(((size_t)(b * SEQLEN + s) * NHEADS) + h) * HDIM + d0 + threadIdx.x];
    }
    __syncthreads();
#pragma unroll
    for (int i = 0; i < 4; i++) {
        int d = d0 + threadIdx.y + i * 8;
        float v = t[threadIdx.x][threadIdx.y + i * 8];
        size_t o = ((size_t)bh * HDIM + d) * SEQLEN + s0 + threadIdx.x;
        vt16[o] = __float2half_rn(v);
    }
}

// ---------------------------------------------------------------------------
// Flash attention, 1-term fp16 mma.sync, 2 CTAs/SM (reg cap 128).
// CTA: 128 q-rows x (head, batch). 8 warps, warp owns 16 q-rows.
// ---------------------------------------------------------------------------
__global__ __launch_bounds__(256, 2)
void flash_attn(const __half* __restrict__ Q16,
                const __half* __restrict__ K16,
                const __half* __restrict__ Vt16,
                __half* __restrict__ Oh) {
    extern __shared__ char sm_raw[];
    const uint32_t base = smem_u32(sm_raw);
    const int tid = threadIdx.x, warp = tid >> 5, lane = tid & 31;
    const int qt = blockIdx.x, h = blockIdx.y, b = blockIdx.z;
    const size_t bhd = (size_t)(b * NHEADS + h);

    const uint32_t sQ = base;
    const uint32_t sKV = base + Q_BYTES;

    {
        const char* gq = (const char*)(Q16 + (bhd * SEQLEN + qt * 128) * HDIM);
        int row = tid >> 4, ch = tid & 15;
#pragma unroll
        for (int i = 0; i < 8; i++) {
            int r = row + i * 16;
            cp16(sQ + r * AQ_STRIDE + ch * 16, gq + r * 256 + ch * 16);
        }
    }

#define LOADKV(kb_, p_)                                                              \
    do {                                                                             \
        uint32_t kvb_ = sKV + (p_) * KVBUF_BYTES;                                    \
        const char* gk_ = (const char*)(K16 + (bhd * SEQLEN + (kb_) * 64) * HDIM);   \
        {                                                                            \
            int row_ = tid >> 4, ch_ = tid & 15;                                     \
            _Pragma("unroll")                                                        \
            for (int i_ = 0; i_ < 4; i_++) {                                         \
                int r_ = row_ + i_ * 16;                                             \
                cp16(kvb_ + r_ * AQ_STRIDE + ch_ * 16, gk_ + r_ * 256 + ch_ * 16);   \
            }                                                                        \
        }                                                                            \
        const char* gv_ = (const char*)(Vt16 + bhd * HDIM * SEQLEN + (kb_) * 64);    \
        {                                                                            \
            int row_ = tid >> 3, ch_ = tid & 7;                                      \
            _Pragma("unroll")                                                        \
            for (int i_ = 0; i_ < 4; i_++) {                                         \
                int r_ = row_ + i_ * 32;                                             \
                cp16(kvb_ + K_BYTES + r_ * AV_STRIDE + ch_ * 16,                     \
                     gv_ + (size_t)r_ * SEQLEN * 2 + ch_ * 16);                      \
            }                                                                        \
        }                                                                            \
        asm volatile("cp.async.commit_group;" ::: "memory");                         \
    } while (0)

    const int nt = 2 * qt + 2;
    LOADKV(0, 0);
    LOADKV(1, 1);

    const uint32_t aQoff = (warp * 16 + (lane & 15)) * AQ_STRIDE + ((lane >> 4) << 4);
    const uint32_t bKoff = ((lane & 7) + ((lane & 16) >> 1)) * AQ_STRIDE + (lane & 8) * 2;
    const uint32_t bVoff = ((lane & 7) + ((lane & 16) >> 1)) * AV_STRIDE + (lane & 8) * 2;

    float o[16][4];
#pragma unroll
    for (int j = 0; j < 16; j++)
#pragma unroll
        for (int c = 0; c < 4; c++) o[j][c] = 0.f;
    float m_run[2] = {-1e30f, -1e30f}, l_run[2] = {0.f, 0.f};

    for (int kb = 0; kb < nt; kb++) {
        const uint32_t kvb = sKV + (kb & 1) * KVBUF_BYTES;
        if (kb + 1 < nt) asm volatile("cp.async.wait_group 1;" ::: "memory");
        else             asm volatile("cp.async.wait_group 0;" ::: "memory");
        __syncthreads();

        // ---- S = Q @ K^T (1 fp16 term) ----
        float s[8][4];
#pragma unroll
        for (int j = 0; j < 8; j++)
#pragma unroll
            for (int c = 0; c < 4; c++) s[j][c] = 0.f;

#pragma unroll
        for (int ks = 0; ks < 8; ks++) {
            uint32_t ah[4];
            ldsm4(ah, sQ + aQoff + ks * 32);
#pragma unroll
            for (int nb = 0; nb < 4; nb++) {
                uint32_t kh4[4];
                ldsm4(kh4, kvb + bKoff + nb * 16 * AQ_STRIDE + ks * 32);
                mma_f16(s[nb * 2], ah, kh4);
                mma_f16(s[nb * 2 + 1], ah, kh4 + 2);
            }
        }

        if (kb >= 2 * qt) {
            int r0 = qt * 128 + warp * 16 + (lane >> 2);
            int c0 = kb * 64 + (lane & 3) * 2;
#pragma unroll
            for (int j = 0; j < 8; j++)
#pragma unroll
                for (int c = 0; c < 4; c++) {
                    int col = c0 + j * 8 + (c & 1);
                    int row = r0 + ((c & 2) ? 8 : 0);
                    if (col > row) s[j][c] = -1e30f;
                }
        }

        float mloc[2] = {-1e30f, -1e30f};
#pragma unroll
        for (int j = 0; j < 8; j++) {
            mloc[0] = fmaxf(mloc[0], fmaxf(s[j][0], s[j][1]));
            mloc[1] = fmaxf(mloc[1], fmaxf(s[j][2], s[j][3]));
        }
        float mnew[2], alpha[2], rs[2];
#pragma unroll
        for (int h2 = 0; h2 < 2; h2++) {
            mloc[h2] = fmaxf(mloc[h2], __shfl_xor_sync(0xffffffffu, mloc[h2], 1));
            mloc[h2] = fmaxf(mloc[h2], __shfl_xor_sync(0xffffffffu, mloc[h2], 2));
            mnew[h2] = fmaxf(m_run[h2], mloc[h2]);
            alpha[h2] = exp2f(m_run[h2] - mnew[h2]);
            rs[h2] = 0.f;
        }
#pragma unroll
        for (int j = 0; j < 8; j++) {
            s[j][0] = exp2f(s[j][0] - mnew[0]);
            s[j][1] = exp2f(s[j][1] - mnew[0]);
            s[j][2] = exp2f(s[j][2] - mnew[1]);
            s[j][3] = exp2f(s[j][3] - mnew[1]);
            rs[0] += s[j][0] + s[j][1];
            rs[1] += s[j][2] + s[j][3];
        }
#pragma unroll
        for (int h2 = 0; h2 < 2; h2++) {
            rs[h2] += __shfl_xor_sync(0xffffffffu, rs[h2], 1);
            rs[h2] += __shfl_xor_sync(0xffffffffu, rs[h2], 2);
            l_run[h2] = l_run[h2] * alpha[h2] + rs[h2];
            m_run[h2] = mnew[h2];
        }
#pragma unroll
        for (int j = 0; j < 16; j++) {
            o[j][0] *= alpha[0];
            o[j][1] *= alpha[0];
            o[j][2] *= alpha[1];
            o[j][3] *= alpha[1];
        }

        // ---- O += P @ V (1 fp16 term) ----
#pragma unroll
        for (int kc = 0; kc < 4; kc++) {
            uint32_t pa[4];
            __half2 p0 = __floats2half2_rn(s[2 * kc][0], s[2 * kc][1]);
            __half2 p1 = __floats2half2_rn(s[2 * kc][2], s[2 * kc][3]);
            __half2 p2 = __floats2half2_rn(s[2 * kc + 1][0], s[2 * kc + 1][1]);
            __half2 p3 = __floats2half2_rn(s[2 * kc + 1][2], s[2 * kc + 1][3]);
            pa[0] = *(uint32_t*)&p0;
            pa[1] = *(uint32_t*)&p1;
            pa[2] = *(uint32_t*)&p2;
            pa[3] = *(uint32_t*)&p3;
#pragma unroll
            for (int nb = 0; nb < 8; nb++) {
                uint32_t vh4[4];
                ldsm4(vh4, kvb + K_BYTES + bVoff + nb * 16 * AV_STRIDE + kc * 32);
                mma_f16(o[nb * 2], pa, vh4);
                mma_f16(o[nb * 2 + 1], pa, vh4 + 2);
            }
        }

        if (kb + 2 < nt) {
            __syncthreads();
            LOADKV(kb + 2, kb & 1);
        }
    }

    // normalize + write fp16 in 256-row tiled-A layout for Wo GEMM
    float inv[2] = {1.f / l_run[0], 1.f / l_run[1]};
    int trow = b * SEQLEN + qt * 128 + warp * 16 + (lane >> 2);
#pragma unroll
    for (int j = 0; j < 16; j++) {
        int c0 = j * 8 + (lane & 3) * 2;
        int k = h * HDIM + c0;
        int ck = k >> 5, c16 = (k & 31) >> 3, bo = (k & 7) * 2;
#pragma unroll
        for (int h2 = 0; h2 < 2; h2++) {
            int t = trow + h2 * 8;
            int mtA = t >> 8, rr = t & 255;
            size_t off = ((((size_t)(mtA * 128 + ck)) * 256 + rr) << 6) +
                         ((c16 ^ ((rr >> 1) & 3)) << 4) + bo;
            __half2 hv = __floats2half2_rn(o[j][h2 * 2] * inv[h2],
                                           o[j][h2 * 2 + 1] * inv[h2]);
            *(uint32_t*)((char*)Oh + off) = *(uint32_t*)&hv;
        }
    }
}

// ---------------------------------------------------------------------------
extern "C" void kernel_launch(void* const* d_in, const int* in_sizes, int n_in,
                              void* d_out, int out_size) {
    const float* x  = (const float*)d_in[0];
    const float* fc = (const float*)d_in[1];
    const float* wq = (const float*)d_in[4];
    const float* wk = (const float*)d_in[5];
    const float* wv = (const float*)d_in[6];
    const float* wo = (const float*)d_in[7];

    float* out = (float*)d_out;
    float* Kh = out + OUT_ELEMS;
    float* Vh = Kh + OUT_ELEMS;

    float* qbuf;
    __half *xh, *wh, *ah, *q16, *k16, *vt16;
    cudaGetSymbolAddress((void**)&qbuf, g_Q);
    cudaGetSymbolAddress((void**)&xh, g_xh);
    cudaGetSymbolAddress((void**)&wh, g_wh);
    cudaGetSymbolAddress((void**)&ah, g_ah);
    cudaGetSymbolAddress((void**)&q16, g_q16);
    cudaGetSymbolAddress((void**)&k16, g_k16);
    cudaGetSymbolAddress((void**)&vt16, g_vt16);

    const int cblocks = (int)(WSZ / 8 / 256);   // 8 elems per thread

    convert_all<<<dim3(cblocks, 5), 256>>>(x, wq, wk, wv, wo, xh, wh);

    cudaFuncSetAttribute(gemm_f16, cudaFuncAttributeMaxDynamicSharedMemorySize, GEMM_SMEM);

    // Fused QKV projection (B tiles 0..95 span wq, wk, wv)
    gemm_f16<<<dim3(96, NTOK / 256), 256, GEMM_SMEM>>>(xh, wh, qbuf, Kh, Vh);

    int rtotal = BSZ * SEQLEN * NHEADS * (HDIM / 2);
    rotary_convert<<<rtotal / 256, 256>>>(qbuf, Kh, fc, q16, k16);
    v_transpose<<<dim3(SEQLEN / 32, HDIM / 32, BSZ * NHEADS), dim3(32, 8)>>>(Vh, vt16);

    cudaFuncSetAttribute(flash_attn, cudaFuncAttributeMaxDynamicSharedMemorySize, ATTN_SMEM);
    flash_attn<<<dim3(SEQLEN / 128, NHEADS, BSZ), 256, ATTN_SMEM>>>(q16, k16, vt16, ah);

    // Output projection
    gemm_f16<<<dim3(32, NTOK / 256), 256, GEMM_SMEM>>>(ah, wh + 3 * WSZ, out, out, out);
}

// round 14
// speedup vs baseline: 1.0377x; 1.0171x over previous
#include <cuda_runtime.h>
#include <cuda_bf16.h>
#include <cuda_fp16.h>
#include <cstdint>

#define BSZ 2
#define SEQLEN 2048
#define NHEADS 32
#define HDIM 128
#define DIM 4096
#define NTOK (BSZ * SEQLEN)              // 4096
#define OUT_ELEMS ((size_t)NTOK * DIM)   // 16,777,216
#define WSZ ((size_t)DIM * DIM)

// ---------------- GEMM tiling: 256x128 CTA tile, BK=32, 1-term fp16 ---------
#define BK 32
#define CHUNKS (DIM / BK)                // 128
#define A_TILE_B 16384                   // 256 rows x 64 B
#define B_TILE_B 8192                    // 128 rows x 64 B
#define STAGE_B (A_TILE_B + B_TILE_B)    // 24576
#define NSTAGE 8
#define GEMM_SMEM (NSTAGE * STAGE_B + 64)       // 196672 B

// ---------------- attention tiling: 1-term fp16, bulk-copy, 2 CTAs/SM -------
#define QT_BYTES 32768                   // Q tile: 4 chunks x 128 rows x 64B
#define KT_BYTES 16384                   // K tile: 4 chunks x 64 rows x 64B
#define VT_BYTES 16384                   // Vt tile: 2 chunks x 128 rows x 64B
#define KV_STAGE (KT_BYTES + VT_BYTES)   // 32768
#define ATTN_SMEM (QT_BYTES + 2 * KV_STAGE + 64)   // 98368 (x2 CTAs fits 227KB)

// ---------------- scratch (device globals; no allocation allowed) -----------
__device__ __align__(256) float g_Q[OUT_ELEMS];
__device__ __align__(256) __half g_xh[OUT_ELEMS];       // x fp16 (A layout)
__device__ __align__(256) __half g_wh[4ull * WSZ];      // weights fp16 (B layout)
__device__ __align__(256) __half g_ah[OUT_ELEMS];       // attn out fp16 (A layout)
__device__ __align__(256) __half g_q16[OUT_ELEMS];      // rotated Q fp16, tiled
__device__ __align__(256) __half g_k16[OUT_ELEMS];      // rotated K fp16, tiled
__device__ __align__(256) __half g_vt16[OUT_ELEMS];     // V^T fp16, tiled

// ---------------- PTX helpers ------------------------------------------------
__device__ __forceinline__ uint32_t smem_u32(const void* p) {
    uint32_t a;
    asm("{ .reg .u64 t; cvta.to.shared.u64 t, %1; cvt.u32.u64 %0, t; }" : "=r"(a) : "l"(p));
    return a;
}
__device__ __forceinline__ void bulk_cp(uint32_t dst, const void* src, uint32_t bytes,
                                        uint32_t mbar) {
    asm volatile(
        "cp.async.bulk.shared::cta.global.mbarrier::complete_tx::bytes [%0], [%1], %2, [%3];"
        :: "r"(dst), "l"(src), "r"(bytes), "r"(mbar) : "memory");
}
__device__ __forceinline__ void mbar_expect(uint32_t mbar, uint32_t bytes) {
    asm volatile("mbarrier.arrive.expect_tx.shared.b64 _, [%0], %1;"
                 :: "r"(mbar), "r"(bytes) : "memory");
}
__device__ __forceinline__ void mbar_wait(uint32_t mbar, uint32_t parity) {
    asm volatile(
        "{\n\t.reg .pred P;\n\t"
        "LAB%=:\n\t"
        "mbarrier.try_wait.parity.acquire.cta.shared::cta.b64 P, [%0], %1, 0x989680;\n\t"
        "@!P bra LAB%=;\n\t}"
        :: "r"(mbar), "r"(parity) : "memory");
}
__device__ __forceinline__ void ldsm4(uint32_t* r, uint32_t addr) {
    asm volatile("ldmatrix.sync.aligned.m8n8.x4.shared.b16 {%0,%1,%2,%3}, [%4];"
        : "=r"(r[0]), "=r"(r[1]), "=r"(r[2]), "=r"(r[3]) : "r"(addr));
}
__device__ __forceinline__ void mma_f16(float* c, const uint32_t* a, const uint32_t* b) {
    asm volatile("mma.sync.aligned.m16n8k16.row.col.f32.f16.f16.f32 "
        "{%0,%1,%2,%3}, {%4,%5,%6,%7}, {%8,%9}, {%0,%1,%2,%3};"
        : "+f"(c[0]), "+f"(c[1]), "+f"(c[2]), "+f"(c[3])
        : "r"(a[0]), "r"(a[1]), "r"(a[2]), "r"(a[3]), "r"(b[0]), "r"(b[1]));
}

// ---------------------------------------------------------------------------
// Combined conversion: blockIdx.y = 0 -> x into A layout (256-row tiles);
// 1..4 -> wq/wk/wv/wo into B layout (128-row tiles).
// ---------------------------------------------------------------------------
__global__ __launch_bounds__(256) void convert_all(
        const float* __restrict__ x,
        const float* __restrict__ w0, const float* __restrict__ w1,
        const float* __restrict__ w2, const float* __restrict__ w3,
        __half* __restrict__ xh, __half* __restrict__ wh) {
    int m = blockIdx.y;
    const float* src = (m == 0) ? x : (m == 1) ? w0 : (m == 2) ? w1 : (m == 3) ? w2 : w3;

    int idx = blockIdx.x * 256 + threadIdx.x;
    int r = idx >> 9;
    int k = (idx & 511) << 3;
    const float4* s = (const float4*)(src + ((size_t)r << 12) + k);
    float4 v0 = s[0], v1 = s[1];
    float f[8] = {v0.x, v0.y, v0.z, v0.w, v1.x, v1.y, v1.z, v1.w};
    __half h8[8];
#pragma unroll
    for (int j = 0; j < 8; j++) h8[j] = __float2half_rn(f[j]);
    int ck = k >> 5, c16 = (k & 31) >> 3;
    if (m == 0) {
        int mt = r >> 8, rr = r & 255;
        size_t off = ((((size_t)(mt * 128 + ck)) * 256 + rr) << 6) +
                     ((c16 ^ ((rr >> 1) & 3)) << 4);
        *(uint4*)((char*)xh + off) = *(uint4*)h8;
    } else {
        __half* hi = wh + (size_t)(m - 1) * WSZ;
        int nt = r >> 7, rr = r & 127;
        size_t off = ((((size_t)(nt * 128 + ck)) * 128 + rr) << 6) +
                     ((c16 ^ ((rr >> 1) & 3)) << 4);
        *(uint4*)((char*)hi + off) = *(uint4*)h8;
    }
}

// ---------------------------------------------------------------------------
// fp16 1-term GEMM (unchanged, known-good). Output routed by nt>>5.
// ---------------------------------------------------------------------------
__global__ __launch_bounds__(256)
void gemm_f16(const __half* __restrict__ Ah, const __half* __restrict__ Bh,
              float* __restrict__ C0, float* __restrict__ C1, float* __restrict__ C2) {
    extern __shared__ char sm_raw[];
    const uint32_t base = smem_u32(sm_raw);
    const uint32_t mb = base + NSTAGE * STAGE_B;
    const int tid = threadIdx.x;
    const int warp = tid >> 5, lane = tid & 31;
    const int wm = warp & 3, wn = warp >> 2;
    const int nt = blockIdx.x, mt = blockIdx.y;
    const size_t mtC = (size_t)mt * CHUNKS;
    const size_t ntC = (size_t)nt * CHUNKS;

    if (tid == 0) {
#pragma unroll
        for (int s = 0; s < NSTAGE; s++)
            asm volatile("mbarrier.init.shared.b64 [%0], %1;" :: "r"(mb + 8 * s), "r"(1u) : "memory");
        asm volatile("fence.proxy.async.shared::cta;" ::: "memory");
    }
    __syncthreads();

#define ISSUE(c, s)                                                              \
    do {                                                                         \
        if (tid == 0) {                                                          \
            uint32_t mb_ = mb + 8 * (s);                                         \
            mbar_expect(mb_, STAGE_B);                                           \
            uint32_t st_ = base + (s) * STAGE_B;                                 \
            bulk_cp(st_, (const char*)Ah + (mtC + (c)) * A_TILE_B, A_TILE_B, mb_); \
            bulk_cp(st_ + A_TILE_B, (const char*)Bh + (ntC + (c)) * B_TILE_B, B_TILE_B, mb_); \
        }                                                                        \
    } while (0)

#pragma unroll
    for (int p = 0; p < NSTAGE - 1; p++) ISSUE(p, p);

    const int rowA = wm * 64 + (lane & 15);
    const int xa = (rowA >> 1) & 3;
    const int lsA = lane >> 4;
    const uint32_t cA0 = (uint32_t)((lsA ^ xa) << 4);
    const uint32_t cA1 = (uint32_t)(((2 | lsA) ^ xa) << 4);
    const uint32_t aRow = (uint32_t)rowA * 64;

    const int rowB = wn * 64 + (lane & 7) + ((lane & 16) >> 1);
    const int xb = (rowB >> 1) & 3;
    const int lsB = (lane & 8) >> 3;
    const uint32_t cB0 = (uint32_t)((lsB ^ xb) << 4);
    const uint32_t cB1 = (uint32_t)(((2 | lsB) ^ xb) << 4);
    const uint32_t bRow = (uint32_t)rowB * 64;

    float c[4][8][4];
#pragma unroll
    for (int mi = 0; mi < 4; mi++)
#pragma unroll
        for (int ni = 0; ni < 8; ni++)
#pragma unroll
            for (int j = 0; j < 4; j++) c[mi][ni][j] = 0.f;

    for (int ck = 0; ck < CHUNKS; ck++) {
        const int s = ck & 7;
        mbar_wait(mb + 8 * s, (ck >> 3) & 1);

        const uint32_t sb = base + s * STAGE_B;
        const uint32_t aHi = sb + aRow;
        const uint32_t bHi = sb + A_TILE_B + bRow;

#pragma unroll
        for (int kk = 0; kk < 2; kk++) {
            const uint32_t ca = kk ? cA1 : cA0;
            const uint32_t cb = kk ? cB1 : cB0;
            uint32_t bh[16];
#pragma unroll
            for (int g = 0; g < 4; g++) ldsm4(bh + g * 4, bHi + g * 1024 + cb);
#pragma unroll
            for (int mi = 0; mi < 4; mi++) {
                uint32_t ah[4];
                ldsm4(ah, aHi + mi * 1024 + ca);
#pragma unroll
                for (int ni = 0; ni < 8; ni++)
                    mma_f16(c[mi][ni], ah, &bh[ni * 2]);
            }
        }
        __syncthreads();
        if (ck + NSTAGE - 1 < CHUNKS) ISSUE(ck + NSTAGE - 1, (ck + NSTAGE - 1) & 7);
    }

    float* Cb = (nt < 32) ? C0 : (nt < 64) ? C1 : C2;
    float* Cw = Cb + (size_t)(mt * 256 + wm * 64) * DIM + (nt & 31) * 128 + wn * 64;
    const int cr = lane >> 2, cc = (lane & 3) * 2;
#pragma unroll
    for (int mi = 0; mi < 4; mi++)
#pragma unroll
        for (int ni = 0; ni < 8; ni++) {
            float* p0 = Cw + (size_t)(mi * 16 + cr) * DIM + ni * 8 + cc;
            float* p1 = p0 + 8 * DIM;
            *(float2*)p0 = make_float2(c[mi][ni][0], c[mi][ni][1]);
            *(float2*)p1 = make_float2(c[mi][ni][2], c[mi][ni][3]);
        }
}

// ---------------------------------------------------------------------------
// Rotary: Q (scaled) and K -> fp16 in swizzled tiled layouts; K fp32 in place.
// Q layout: (bhd*16 + s>>7) tiles of 32KB: [ck(4)][rr=s&127][64B swizzled]
// K layout: (bhd*32 + s>>6) tiles of 16KB: [ck(4)][rr=s&63][64B swizzled]
// ---------------------------------------------------------------------------
__global__ __launch_bounds__(256) void rotary_convert(
        const float* __restrict__ Q, float* __restrict__ Kf,
        const float* __restrict__ fc,
        __half* __restrict__ q16, __half* __restrict__ k16) {
    const float QSC = 1.44269504088896f / 11.3137084989848f;
    int idx = blockIdx.x * blockDim.x + threadIdx.x;
    int p = idx & 63;
    int h = (idx >> 6) & 31;
    int s = (idx >> 11) & (SEQLEN - 1);
    int b = idx >> 22;
    int bhd = b * NHEADS + h;

    float c = fc[(s * 64 + p) * 2];
    float sn = fc[(s * 64 + p) * 2 + 1];

    size_t in = (((size_t)(b * SEQLEN + s) * NHEADS) + h) * HDIM + p * 2;

    float2 q = *(float2*)(Q + in);
    float2 k = *(float2*)(Kf + in);
    float2 qo = {q.x * c - q.y * sn, q.x * sn + q.y * c};
    float2 ko = {k.x * c - k.y * sn, k.x * sn + k.y * c};
    *(float2*)(Kf + in) = ko;

    int d = p * 2;
    int ck = d >> 5, c16 = (d & 31) >> 3, eo = (d & 7) * 2;

    // Q: tile = s>>7, rr = s&127
    {
        int rr = s & 127;
        size_t off = ((size_t)(bhd * 16 + (s >> 7))) * QT_BYTES +
                     ck * 8192 + rr * 64 + ((c16 ^ ((rr >> 1) & 3)) << 4) + eo;
        __half2 hv = __floats2half2_rn(qo.x * QSC, qo.y * QSC);
        *(uint32_t*)((char*)q16 + off) = *(uint32_t*)&hv;
    }
    // K: tile = s>>6, rr = s&63
    {
        int rr = s & 63;
        size_t off = ((size_t)(bhd * 32 + (s >> 6))) * KT_BYTES +
                     ck * 4096 + rr * 64 + ((c16 ^ ((rr >> 1) & 3)) << 4) + eo;
        __half2 hv = __floats2half2_rn(ko.x, ko.y);
        *(uint32_t*)((char*)k16 + off) = *(uint32_t*)&hv;
    }
}

// ---------------------------------------------------------------------------
// V transpose: fp32 [B,S,H,D] -> fp16 tiled Vt layout:
// (bhd*32 + s>>6) tiles of 16KB: [cs=(s&63)>>5][rr=d][64B swizzled, col s&31]
// ---------------------------------------------------------------------------
__global__ __launch_bounds__(256) void v_transpose(const float* __restrict__ V,
                                                   __half* __restrict__ vt16) {
    __shared__ float t[32][33];
    int s0 = blockIdx.x * 32, d0 = blockIdx.y * 32;
    int bh = blockIdx.z;
    int b = bh >> 5, h = bh & 31;
#pragma unroll
    for (int i = 0; i < 4; i++) {
        int s = s0 + threadIdx.y + i * 8;
        t[threadIdx.y + i * 8][threadIdx.x] =
            V[(((size_t)(b * SEQLEN + s) * NHEADS) + h) * HDIM + d0 + threadIdx.x];
    }
    __syncthreads();
    int s = s0 + threadIdx.x;
    int kb = s >> 6, cs = (s & 63) >> 5, c16 = (s & 31) >> 3, eo = (s & 7) * 2;
#pragma unroll
    for (int i = 0; i < 4; i++) {
        int d = d0 + threadIdx.y + i * 8;
        float v = t[threadIdx.x][threadIdx.y + i * 8];
        size_t off = ((size_t)(bh * 32 + kb)) * VT_BYTES +
                     cs * 8192 + d * 64 + ((c16 ^ ((d >> 1) & 3)) << 4) + eo;
        *(__half*)((char*)vt16 + off) = __float2half_rn(v);
    }
}

// ---------------------------------------------------------------------------
// Flash attention, 1-term fp16 mma.sync, bulk-copy loads, 2 CTAs/SM.
// CTA: 128 q-rows x (head, batch). 8 warps, warp owns 16 q-rows.
// ---------------------------------------------------------------------------
__global__ __launch_bounds__(256, 2)
void flash_attn(const __half* __restrict__ Q16,
                const __half* __restrict__ K16,
                const __half* __restrict__ Vt16,
                __half* __restrict__ Oh) {
    extern __shared__ char sm_raw[];
    const uint32_t base = smem_u32(sm_raw);
    const int tid = threadIdx.x, warp = tid >> 5, lane = tid & 31;
    const int qt = blockIdx.x, h = blockIdx.y, b = blockIdx.z;
    const int bhd = b * NHEADS + h;

    const uint32_t sQ = base;
    const uint32_t sKV = base + QT_BYTES;
    const uint32_t mb = base + QT_BYTES + 2 * KV_STAGE;   // mbQ, mb0, mb1

    const char* qsrc = (const char*)Q16 + ((size_t)(bhd * 16 + qt)) * QT_BYTES;
    const char* ksrc = (const char*)K16 + ((size_t)(bhd * 32)) * KT_BYTES;
    const char* vsrc = (const char*)Vt16 + ((size_t)(bhd * 32)) * VT_BYTES;

    if (tid == 0) {
#pragma unroll
        for (int s = 0; s < 3; s++)
            asm volatile("mbarrier.init.shared.b64 [%0], %1;" :: "r"(mb + 8 * s), "r"(1u) : "memory");
        asm volatile("fence.proxy.async.shared::cta;" ::: "memory");
    }
    __syncthreads();

#define ISSUEKV(kb_, st_)                                                        \
    do {                                                                         \
        uint32_t mb_ = mb + 8 + 8 * (st_);                                       \
        mbar_expect(mb_, KV_STAGE);                                              \
        uint32_t dst_ = sKV + (st_) * KV_STAGE;                                  \
        bulk_cp(dst_, ksrc + (size_t)(kb_) * KT_BYTES, KT_BYTES, mb_);           \
        bulk_cp(dst_ + KT_BYTES, vsrc + (size_t)(kb_) * VT_BYTES, VT_BYTES, mb_); \
    } while (0)

    const int nt = 2 * qt + 2;
    if (tid == 0) {
        mbar_expect(mb, QT_BYTES);
        bulk_cp(sQ, qsrc, QT_BYTES, mb);
        ISSUEKV(0, 0);
        ISSUEKV(1, 1);
    }

    // ldsm address components (swizzled 64B rows, GEMM-proven pattern)
    const int rowA = warp * 16 + (lane & 15);
    const int xa = (rowA >> 1) & 3;
    const int lsA = lane >> 4;
    const uint32_t cA0 = (uint32_t)((lsA ^ xa) << 4);
    const uint32_t cA1 = (uint32_t)(((2 | lsA) ^ xa) << 4);
    const uint32_t aRow = sQ + (uint32_t)rowA * 64;

    const int rowBl = (lane & 7) + ((lane & 16) >> 1);
    const int xb = (rowBl >> 1) & 3;
    const int lsB = (lane & 8) >> 3;
    const uint32_t cB0 = (uint32_t)((lsB ^ xb) << 4);
    const uint32_t cB1 = (uint32_t)(((2 | lsB) ^ xb) << 4);
    const uint32_t bRow = (uint32_t)rowBl * 64;

    float o[16][4];
#pragma unroll
    for (int j = 0; j < 16; j++)
#pragma unroll
        for (int c = 0; c < 4; c++) o[j][c] = 0.f;
    float m_run[2] = {-1e30f, -1e30f}, l_run[2] = {0.f, 0.f};

    mbar_wait(mb, 0);   // Q ready

    for (int kb = 0; kb < nt; kb++) {
        const int st = kb & 1;
        mbar_wait(mb + 8 + 8 * st, (kb >> 1) & 1);
        const uint32_t sK = sKV + st * KV_STAGE;
        const uint32_t sV = sK + KT_BYTES;

        // ---- S = Q @ K^T (1 fp16 term) ----
        float s[8][4];
#pragma unroll
        for (int j = 0; j < 8; j++)
#pragma unroll
            for (int c = 0; c < 4; c++) s[j][c] = 0.f;

#pragma unroll
        for (int ks = 0; ks < 8; ks++) {
            uint32_t ah[4];
            ldsm4(ah, aRow + (ks >> 1) * 8192 + ((ks & 1) ? cA1 : cA0));
#pragma unroll
            for (int nb = 0; nb < 4; nb++) {
                uint32_t kh4[4];
                ldsm4(kh4, sK + (ks >> 1) * 4096 + nb * 1024 + bRow + ((ks & 1) ? cB1 : cB0));
                mma_f16(s[nb * 2], ah, kh4);
                mma_f16(s[nb * 2 + 1], ah, kh4 + 2);
            }
        }

        if (kb >= 2 * qt) {
            int r0 = qt * 128 + warp * 16 + (lane >> 2);
            int c0 = kb * 64 + (lane & 3) * 2;
#pragma unroll
            for (int j = 0; j < 8; j++)
#pragma unroll
                for (int c = 0; c < 4; c++) {
                    int col = c0 + j * 8 + (c & 1);
                    int row = r0 + ((c & 2) ? 8 : 0);
                    if (col > row) s[j][c] = -1e30f;
                }
        }

        float mloc[2] = {-1e30f, -1e30f};
#pragma unroll
        for (int j = 0; j < 8; j++) {
            mloc[0] = fmaxf(mloc[0], fmaxf(s[j][0], s[j][1]));
            mloc[1] = fmaxf(mloc[1], fmaxf(s[j][2], s[j][3]));
        }
        float mnew[2], alpha[2], rs[2];
#pragma unroll
        for (int h2 = 0; h2 < 2; h2++) {
            mloc[h2] = fmaxf(mloc[h2], __shfl_xor_sync(0xffffffffu, mloc[h2], 1));
            mloc[h2] = fmaxf(mloc[h2], __shfl_xor_sync(0xffffffffu, mloc[h2], 2));
            mnew[h2] = fmaxf(m_run[h2], mloc[h2]);
            alpha[h2] = exp2f(m_run[h2] - mnew[h2]);
            rs[h2] = 0.f;
        }
#pragma unroll
        for (int j = 0; j < 8; j++) {
            s[j][0] = exp2f(s[j][0] - mnew[0]);
            s[j][1] = exp2f(s[j][1] - mnew[0]);
            s[j][2] = exp2f(s[j][2] - mnew[1]);
            s[j][3] = exp2f(s[j][3] - mnew[1]);
            rs[0] += s[j][0] + s[j][1];
            rs[1] += s[j][2] + s[j][3];
        }
#pragma unroll
        for (int h2 = 0; h2 < 2; h2++) {
            rs[h2] += __shfl_xor_sync(0xffffffffu, rs[h2], 1);
            rs[h2] += __shfl_xor_sync(0xffffffffu, rs[h2], 2);
            l_run[h2] = l_run[h2] * alpha[h2] + rs[h2];
            m_run[h2] = mnew[h2];
        }
#pragma unroll
        for (int j = 0; j < 16; j++) {
            o[j][0] *= alpha[0];
            o[j][1] *= alpha[0];
            o[j][2] *= alpha[1];
            o[j][3] *= alpha[1];
        }

        // ---- O += P @ V (1 fp16 term) ----
#pragma unroll
        for (int kc = 0; kc < 4; kc++) {
            uint32_t pa[4];
            __half2 p0 = __floats2half2_rn(s[2 * kc][0], s[2 * kc][1]);
            __half2 p1 = __floats2half2_rn(s[2 * kc][2], s[2 * kc][3]);
            __half2 p2 = __floats2half2_rn(s[2 * kc + 1][0], s[2 * kc + 1][1]);
            __half2 p3 = __floats2half2_rn(s[2 * kc + 1][2], s[2 * kc + 1][3]);
            pa[0] = *(uint32_t*)&p0;
            pa[1] = *(uint32_t*)&p1;
            pa[2] = *(uint32_t*)&p2;
            pa[3] = *(uint32_t*)&p3;
#pragma unroll
            for (int nb = 0; nb < 8; nb++) {
                uint32_t vh4[4];
                ldsm4(vh4, sV + (kc >> 1) * 8192 + nb * 1024 + bRow + ((kc & 1) ? cB1 : cB0));
                mma_f16(o[nb * 2], pa, vh4);
                mma_f16(o[nb * 2 + 1], pa, vh4 + 2);
            }
        }

        __syncthreads();
        if (tid == 0 && kb + 2 < nt) ISSUEKV(kb + 2, st);
    }

    // normalize + write fp16 in 256-row tiled-A layout for Wo GEMM
    float inv[2] = {1.f / l_run[0], 1.f / l_run[1]};
    int trow = b * SEQLEN + qt * 128 + warp * 16 + (lane >> 2);
#pragma unroll
    for (int j = 0; j < 16; j++) {
        int c0 = j * 8 + (lane & 3) * 2;
        int k = h * HDIM + c0;
        int ck = k >> 5, c16 = (k & 31) >> 3, bo = (k & 7) * 2;
#pragma unroll
        for (int h2 = 0; h2 < 2; h2++) {
            int t = trow + h2 * 8;
            int mtA = t >> 8, rr = t & 255;
            size_t off = ((((size_t)(mtA * 128 + ck)) * 256 + rr) << 6) +
                         ((c16 ^ ((rr >> 1) & 3)) << 4) + bo;
            __half2 hv = __floats2half2_rn(o[j][h2 * 2] * inv[h2],
                                           o[j][h2 * 2 + 1] * inv[h2]);
            *(uint32_t*)((char*)Oh + off) = *(uint32_t*)&hv;
        }
    }
}

// ---------------------------------------------------------------------------
extern "C" void kernel_launch(void* const* d_in, const int* in_sizes, int n_in,
                              void* d_out, int out_size) {
    const float* x  = (const float*)d_in[0];
    const float* fc = (const float*)d_in[1];
    const float* wq = (const float*)d_in[4];
    const float* wk = (const float*)d_in[5];
    const float* wv = (const float*)d_in[6];
    const float* wo = (const float*)d_in[7];

    float* out = (float*)d_out;
    float* Kh = out + OUT_ELEMS;
    float* Vh = Kh + OUT_ELEMS;

    float* qbuf;
    __half *xh, *wh, *ah, *q16, *k16, *vt16;
    cudaGetSymbolAddress((void**)&qbuf, g_Q);
    cudaGetSymbolAddress((void**)&xh, g_xh);
    cudaGetSymbolAddress((void**)&wh, g_wh);
    cudaGetSymbolAddress((void**)&ah, g_ah);
    cudaGetSymbolAddress((void**)&q16, g_q16);
    cudaGetSymbolAddress((void**)&k16, g_k16);
    cudaGetSymbolAddress((void**)&vt16, g_vt16);

    const int cblocks = (int)(WSZ / 8 / 256);   // 8 elems per thread

    convert_all<<<dim3(cblocks, 5), 256>>>(x, wq, wk, wv, wo, xh, wh);

    cudaFuncSetAttribute(gemm_f16, cudaFuncAttributeMaxDynamicSharedMemorySize, GEMM_SMEM);

    // Fused QKV projection (B tiles 0..95 span wq, wk, wv)
    gemm_f16<<<dim3(96, NTOK / 256), 256, GEMM_SMEM>>>(xh, wh, qbuf, Kh, Vh);

    int rtotal = BSZ * SEQLEN * NHEADS * (HDIM / 2);
    rotary_convert<<<rtotal / 256, 256>>>(qbuf, Kh, fc, q16, k16);
    v_transpose<<<dim3(SEQLEN / 32, HDIM / 32, BSZ * NHEADS), dim3(32, 8)>>>(Vh, vt16);

    cudaFuncSetAttribute(flash_attn, cudaFuncAttributeMaxDynamicSharedMemorySize, ATTN_SMEM);
    flash_attn<<<dim3(SEQLEN / 128, NHEADS, BSZ), 256, ATTN_SMEM>>>(q16, k16, vt16, ah);

    // Output projection
    gemm_f16<<<dim3(32, NTOK / 256), 256, GEMM_SMEM>>>(ah, wh + 3 * WSZ, out, out, out);
}

// round 15
// speedup vs baseline: 1.0428x; 1.0049x over previous
#include <cuda_runtime.h>
#include <cuda_bf16.h>
#include <cuda_fp16.h>
#include <cstdint>

#define BSZ 2
#define SEQLEN 2048
#define NHEADS 32
#define HDIM 128
#define DIM 4096
#define NTOK (BSZ * SEQLEN)              // 4096
#define OUT_ELEMS ((size_t)NTOK * DIM)   // 16,777,216
#define WSZ ((size_t)DIM * DIM)

// ---------------- GEMM tiling: 256x128 CTA tile, BK=32, 1-term fp16 ---------
#define BK 32
#define CHUNKS (DIM / BK)                // 128
#define A_TILE_B 16384                   // 256 rows x 64 B
#define B_TILE_B 8192                    // 128 rows x 64 B
#define STAGE_B (A_TILE_B + B_TILE_B)    // 24576
#define NSTAGE 8
#define GEMM_SMEM (NSTAGE * STAGE_B + 64)       // 196672 B

// ---------------- attention tiling: 1-term fp16, bulk-copy, 2 CTAs/SM -------
#define QT_BYTES 32768                   // Q tile: 4 chunks x 128 rows x 64B
#define KT_BYTES 16384                   // K tile: 4 chunks x 64 rows x 64B
#define VT_BYTES 16384                   // Vt tile: 2 chunks x 128 rows x 64B
#define KV_STAGE (KT_BYTES + VT_BYTES)   // 32768
#define ATTN_SMEM (QT_BYTES + 2 * KV_STAGE + 64)   // 98368 (x2 CTAs fits 227KB)

// ---------------- scratch (device globals; no allocation allowed) -----------
__device__ __align__(256) float g_Q[OUT_ELEMS];
__device__ __align__(256) __half g_xh[OUT_ELEMS];       // x fp16 (A layout)
__device__ __align__(256) __half g_wh[4ull * WSZ];      // weights fp16 (B layout)
__device__ __align__(256) __half g_ah[OUT_ELEMS];       // attn out fp16 (A layout)
__device__ __align__(256) __half g_q16[OUT_ELEMS];      // rotated Q fp16, tiled
__device__ __align__(256) __half g_k16[OUT_ELEMS];      // rotated K fp16, tiled
__device__ __align__(256) __half g_vt16[OUT_ELEMS];     // V^T fp16, tiled

// ---------------- PTX helpers ------------------------------------------------
__device__ __forceinline__ uint32_t smem_u32(const void* p) {
    uint32_t a;
    asm("{ .reg .u64 t; cvta.to.shared.u64 t, %1; cvt.u32.u64 %0, t; }" : "=r"(a) : "l"(p));
    return a;
}
__device__ __forceinline__ void bulk_cp(uint32_t dst, const void* src, uint32_t bytes,
                                        uint32_t mbar) {
    asm volatile(
        "cp.async.bulk.shared::cta.global.mbarrier::complete_tx::bytes [%0], [%1], %2, [%3];"
        :: "r"(dst), "l"(src), "r"(bytes), "r"(mbar) : "memory");
}
__device__ __forceinline__ void mbar_expect(uint32_t mbar, uint32_t bytes) {
    asm volatile("mbarrier.arrive.expect_tx.shared.b64 _, [%0], %1;"
                 :: "r"(mbar), "r"(bytes) : "memory");
}
__device__ __forceinline__ void mbar_wait(uint32_t mbar, uint32_t parity) {
    asm volatile(
        "{\n\t.reg .pred P;\n\t"
        "LAB%=:\n\t"
        "mbarrier.try_wait.parity.acquire.cta.shared::cta.b64 P, [%0], %1, 0x989680;\n\t"
        "@!P bra LAB%=;\n\t}"
        :: "r"(mbar), "r"(parity) : "memory");
}
__device__ __forceinline__ void ldsm4(uint32_t* r, uint32_t addr) {
    asm volatile("ldmatrix.sync.aligned.m8n8.x4.shared.b16 {%0,%1,%2,%3}, [%4];"
        : "=r"(r[0]), "=r"(r[1]), "=r"(r[2]), "=r"(r[3]) : "r"(addr));
}
__device__ __forceinline__ void mma_f16(float* c, const uint32_t* a, const uint32_t* b) {
    asm volatile("mma.sync.aligned.m16n8k16.row.col.f32.f16.f16.f32 "
        "{%0,%1,%2,%3}, {%4,%5,%6,%7}, {%8,%9}, {%0,%1,%2,%3};"
        : "+f"(c[0]), "+f"(c[1]), "+f"(c[2]), "+f"(c[3])
        : "r"(a[0]), "r"(a[1]), "r"(a[2]), "r"(a[3]), "r"(b[0]), "r"(b[1]));
}

// ---------------------------------------------------------------------------
// Combined conversion: blockIdx.y = 0 -> x into A layout (256-row tiles);
// 1..4 -> wq/wk/wv/wo into B layout (128-row tiles).
// ---------------------------------------------------------------------------
__global__ __launch_bounds__(256) void convert_all(
        const float* __restrict__ x,
        const float* __restrict__ w0, const float* __restrict__ w1,
        const float* __restrict__ w2, const float* __restrict__ w3,
        __half* __restrict__ xh, __half* __restrict__ wh) {
    int m = blockIdx.y;
    const float* src = (m == 0) ? x : (m == 1) ? w0 : (m == 2) ? w1 : (m == 3) ? w2 : w3;

    int idx = blockIdx.x * 256 + threadIdx.x;
    int r = idx >> 9;
    int k = (idx & 511) << 3;
    const float4* s = (const float4*)(src + ((size_t)r << 12) + k);
    float4 v0 = s[0], v1 = s[1];
    float f[8] = {v0.x, v0.y, v0.z, v0.w, v1.x, v1.y, v1.z, v1.w};
    __half h8[8];
#pragma unroll
    for (int j = 0; j < 8; j++) h8[j] = __float2half_rn(f[j]);
    int ck = k >> 5, c16 = (k & 31) >> 3;
    if (m == 0) {
        int mt = r >> 8, rr = r & 255;
        size_t off = ((((size_t)(mt * 128 + ck)) * 256 + rr) << 6) +
                     ((c16 ^ ((rr >> 1) & 3)) << 4);
        *(uint4*)((char*)xh + off) = *(uint4*)h8;
    } else {
        __half* hi = wh + (size_t)(m - 1) * WSZ;
        int nt = r >> 7, rr = r & 127;
        size_t off = ((((size_t)(nt * 128 + ck)) * 128 + rr) << 6) +
                     ((c16 ^ ((rr >> 1) & 3)) << 4);
        *(uint4*)((char*)hi + off) = *(uint4*)h8;
    }
}

// ---------------------------------------------------------------------------
// fp16 1-term GEMM (unchanged, known-good). Output routed by nt>>5.
// ---------------------------------------------------------------------------
__global__ __launch_bounds__(256)
void gemm_f16(const __half* __restrict__ Ah, const __half* __restrict__ Bh,
              float* __restrict__ C0, float* __restrict__ C1, float* __restrict__ C2) {
    extern __shared__ char sm_raw[];
    const uint32_t base = smem_u32(sm_raw);
    const uint32_t mb = base + NSTAGE * STAGE_B;
    const int tid = threadIdx.x;
    const int warp = tid >> 5, lane = tid & 31;
    const int wm = warp & 3, wn = warp >> 2;
    const int nt = blockIdx.x, mt = blockIdx.y;
    const size_t mtC = (size_t)mt * CHUNKS;
    const size_t ntC = (size_t)nt * CHUNKS;

    if (tid == 0) {
#pragma unroll
        for (int s = 0; s < NSTAGE; s++)
            asm volatile("mbarrier.init.shared.b64 [%0], %1;" :: "r"(mb + 8 * s), "r"(1u) : "memory");
        asm volatile("fence.proxy.async.shared::cta;" ::: "memory");
    }
    __syncthreads();

#define ISSUE(c, s)                                                              \
    do {                                                                         \
        if (tid == 0) {                                                          \
            uint32_t mb_ = mb + 8 * (s);                                         \
            mbar_expect(mb_, STAGE_B);                                           \
            uint32_t st_ = base + (s) * STAGE_B;                                 \
            bulk_cp(st_, (const char*)Ah + (mtC + (c)) * A_TILE_B, A_TILE_B, mb_); \
            bulk_cp(st_ + A_TILE_B, (const char*)Bh + (ntC + (c)) * B_TILE_B, B_TILE_B, mb_); \
        }                                                                        \
    } while (0)

#pragma unroll
    for (int p = 0; p < NSTAGE - 1; p++) ISSUE(p, p);

    const int rowA = wm * 64 + (lane & 15);
    const int xa = (rowA >> 1) & 3;
    const int lsA = lane >> 4;
    const uint32_t cA0 = (uint32_t)((lsA ^ xa) << 4);
    const uint32_t cA1 = (uint32_t)(((2 | lsA) ^ xa) << 4);
    const uint32_t aRow = (uint32_t)rowA * 64;

    const int rowB = wn * 64 + (lane & 7) + ((lane & 16) >> 1);
    const int xb = (rowB >> 1) & 3;
    const int lsB = (lane & 8) >> 3;
    const uint32_t cB0 = (uint32_t)((lsB ^ xb) << 4);
    const uint32_t cB1 = (uint32_t)(((2 | lsB) ^ xb) << 4);
    const uint32_t bRow = (uint32_t)rowB * 64;

    float c[4][8][4];
#pragma unroll
    for (int mi = 0; mi < 4; mi++)
#pragma unroll
        for (int ni = 0; ni < 8; ni++)
#pragma unroll
            for (int j = 0; j < 4; j++) c[mi][ni][j] = 0.f;

    for (int ck = 0; ck < CHUNKS; ck++) {
        const int s = ck & 7;
        mbar_wait(mb + 8 * s, (ck >> 3) & 1);

        const uint32_t sb = base + s * STAGE_B;
        const uint32_t aHi = sb + aRow;
        const uint32_t bHi = sb + A_TILE_B + bRow;

#pragma unroll
        for (int kk = 0; kk < 2; kk++) {
            const uint32_t ca = kk ? cA1 : cA0;
            const uint32_t cb = kk ? cB1 : cB0;
            uint32_t bh[16];
#pragma unroll
            for (int g = 0; g < 4; g++) ldsm4(bh + g * 4, bHi + g * 1024 + cb);
#pragma unroll
            for (int mi = 0; mi < 4; mi++) {
                uint32_t ah[4];
                ldsm4(ah, aHi + mi * 1024 + ca);
#pragma unroll
                for (int ni = 0; ni < 8; ni++)
                    mma_f16(c[mi][ni], ah, &bh[ni * 2]);
            }
        }
        __syncthreads();
        if (ck + NSTAGE - 1 < CHUNKS) ISSUE(ck + NSTAGE - 1, (ck + NSTAGE - 1) & 7);
    }

    float* Cb = (nt < 32) ? C0 : (nt < 64) ? C1 : C2;
    float* Cw = Cb + (size_t)(mt * 256 + wm * 64) * DIM + (nt & 31) * 128 + wn * 64;
    const int cr = lane >> 2, cc = (lane & 3) * 2;
#pragma unroll
    for (int mi = 0; mi < 4; mi++)
#pragma unroll
        for (int ni = 0; ni < 8; ni++) {
            float* p0 = Cw + (size_t)(mi * 16 + cr) * DIM + ni * 8 + cc;
            float* p1 = p0 + 8 * DIM;
            *(float2*)p0 = make_float2(c[mi][ni][0], c[mi][ni][1]);
            *(float2*)p1 = make_float2(c[mi][ni][2], c[mi][ni][3]);
        }
}

// ---------------------------------------------------------------------------
// Merged pre-attention kernel.
// Blocks [0, 32768): rotary on Q + K -> fp16 tiled layouts (K fp32 in place).
// Blocks [32768, 49152): V transpose -> fp16 tiled Vt layout.
// ---------------------------------------------------------------------------
#define ROT_BLOCKS 32768
__global__ __launch_bounds__(256) void pre_attn(
        const float* __restrict__ Q, float* __restrict__ Kf,
        const float* __restrict__ fc, const float* __restrict__ V,
        __half* __restrict__ q16, __half* __restrict__ k16,
        __half* __restrict__ vt16) {
    const int tid = threadIdx.x;
    if (blockIdx.x < ROT_BLOCKS) {
        const float QSC = 1.44269504088896f / 11.3137084989848f;
        int idx = blockIdx.x * 256 + tid;
        int p = idx & 63;
        int h = (idx >> 6) & 31;
        int s = (idx >> 11) & (SEQLEN - 1);
        int b = idx >> 22;
        int bhd = b * NHEADS + h;

        float c = fc[(s * 64 + p) * 2];
        float sn = fc[(s * 64 + p) * 2 + 1];

        size_t in = (((size_t)(b * SEQLEN + s) * NHEADS) + h) * HDIM + p * 2;

        float2 q = *(float2*)(Q + in);
        float2 k = *(float2*)(Kf + in);
        float2 qo = {q.x * c - q.y * sn, q.x * sn + q.y * c};
        float2 ko = {k.x * c - k.y * sn, k.x * sn + k.y * c};
        *(float2*)(Kf + in) = ko;

        int d = p * 2;
        int ck = d >> 5, c16 = (d & 31) >> 3, eo = (d & 7) * 2;

        {   // Q: tile = s>>7, rr = s&127
            int rr = s & 127;
            size_t off = ((size_t)(bhd * 16 + (s >> 7))) * QT_BYTES +
                         ck * 8192 + rr * 64 + ((c16 ^ ((rr >> 1) & 3)) << 4) + eo;
            __half2 hv = __floats2half2_rn(qo.x * QSC, qo.y * QSC);
            *(uint32_t*)((char*)q16 + off) = *(uint32_t*)&hv;
        }
        {   // K: tile = s>>6, rr = s&63
            int rr = s & 63;
            size_t off = ((size_t)(bhd * 32 + (s >> 6))) * KT_BYTES +
                         ck * 4096 + rr * 64 + ((c16 ^ ((rr >> 1) & 3)) << 4) + eo;
            __half2 hv = __floats2half2_rn(ko.x, ko.y);
            *(uint32_t*)((char*)k16 + off) = *(uint32_t*)&hv;
        }
    } else {
        __shared__ float t[32][33];
        int bid = blockIdx.x - ROT_BLOCKS;       // original grid (64, 4, 64), x fastest
        int s0 = (bid & 63) * 32;
        int d0 = ((bid >> 6) & 3) * 32;
        int bh = bid >> 8;
        int b = bh >> 5, h = bh & 31;
        int tx = tid & 31, ty = tid >> 5;        // (32, 8)
#pragma unroll
        for (int i = 0; i < 4; i++) {
            int s = s0 + ty + i * 8;
            t[ty + i * 8][tx] =
                V[(((size_t)(b * SEQLEN + s) * NHEADS) + h) * HDIM + d0 + tx];
        }
        __syncthreads();
        int s = s0 + tx;
        int kb = s >> 6, cs = (s & 63) >> 5, c16 = (s & 31) >> 3, eo = (s & 7) * 2;
#pragma unroll
        for (int i = 0; i < 4; i++) {
            int d = d0 + ty + i * 8;
            float v = t[tx][ty + i * 8];
            size_t off = ((size_t)(bh * 32 + kb)) * VT_BYTES +
                         cs * 8192 + d * 64 + ((c16 ^ ((d >> 1) & 3)) << 4) + eo;
            *(__half*)((char*)vt16 + off) = __float2half_rn(v);
        }
    }
}

// ---------------------------------------------------------------------------
// Flash attention, 1-term fp16 mma.sync, bulk-copy loads, 2 CTAs/SM.
// qt reversed (long CTAs first); fully-masked warps skip the diagonal tile.
// ---------------------------------------------------------------------------
__global__ __launch_bounds__(256, 2)
void flash_attn(const __half* __restrict__ Q16,
                const __half* __restrict__ K16,
                const __half* __restrict__ Vt16,
                __half* __restrict__ Oh) {
    extern __shared__ char sm_raw[];
    const uint32_t base = smem_u32(sm_raw);
    const int tid = threadIdx.x, warp = tid >> 5, lane = tid & 31;
    const int qt = (gridDim.x - 1) - blockIdx.x;      // long CTAs first
    const int h = blockIdx.y, b = blockIdx.z;
    const int bhd = b * NHEADS + h;

    const uint32_t sQ = base;
    const uint32_t sKV = base + QT_BYTES;
    const uint32_t mb = base + QT_BYTES + 2 * KV_STAGE;   // mbQ, mb0, mb1

    const char* qsrc = (const char*)Q16 + ((size_t)(bhd * 16 + qt)) * QT_BYTES;
    const char* ksrc = (const char*)K16 + ((size_t)(bhd * 32)) * KT_BYTES;
    const char* vsrc = (const char*)Vt16 + ((size_t)(bhd * 32)) * VT_BYTES;

    if (tid == 0) {
#pragma unroll
        for (int s = 0; s < 3; s++)
            asm volatile("mbarrier.init.shared.b64 [%0], %1;" :: "r"(mb + 8 * s), "r"(1u) : "memory");
        asm volatile("fence.proxy.async.shared::cta;" ::: "memory");
    }
    __syncthreads();

#define ISSUEKV(kb_, st_)                                                        \
    do {                                                                         \
        uint32_t mb_ = mb + 8 + 8 * (st_);                                       \
        mbar_expect(mb_, KV_STAGE);                                              \
        uint32_t dst_ = sKV + (st_) * KV_STAGE;                                  \
        bulk_cp(dst_, ksrc + (size_t)(kb_) * KT_BYTES, KT_BYTES, mb_);           \
        bulk_cp(dst_ + KT_BYTES, vsrc + (size_t)(kb_) * VT_BYTES, VT_BYTES, mb_); \
    } while (0)

    const int nt = 2 * qt + 2;
    if (tid == 0) {
        mbar_expect(mb, QT_BYTES);
        bulk_cp(sQ, qsrc, QT_BYTES, mb);
        ISSUEKV(0, 0);
        ISSUEKV(1, 1);
    }

    const int rowA = warp * 16 + (lane & 15);
    const int xa = (rowA >> 1) & 3;
    const int lsA = lane >> 4;
    const uint32_t cA0 = (uint32_t)((lsA ^ xa) << 4);
    const uint32_t cA1 = (uint32_t)(((2 | lsA) ^ xa) << 4);
    const uint32_t aRow = sQ + (uint32_t)rowA * 64;

    const int rowBl = (lane & 7) + ((lane & 16) >> 1);
    const int xb = (rowBl >> 1) & 3;
    const int lsB = (lane & 8) >> 3;
    const uint32_t cB0 = (uint32_t)((lsB ^ xb) << 4);
    const uint32_t cB1 = (uint32_t)(((2 | lsB) ^ xb) << 4);
    const uint32_t bRow = (uint32_t)rowBl * 64;

    float o[16][4];
#pragma unroll
    for (int j = 0; j < 16; j++)
#pragma unroll
        for (int c = 0; c < 4; c++) o[j][c] = 0.f;
    float m_run[2] = {-1e30f, -1e30f}, l_run[2] = {0.f, 0.f};

    mbar_wait(mb, 0);   // Q ready

    for (int kb = 0; kb < nt; kb++) {
        const int st = kb & 1;
        mbar_wait(mb + 8 + 8 * st, (kb >> 1) & 1);
        const uint32_t sK = sKV + st * KV_STAGE;
        const uint32_t sV = sK + KT_BYTES;

        // fully-masked warp on the diagonal tile: exact no-op, skip compute
        const bool active = (kb * 64) <= (qt * 128 + warp * 16 + 15);
        if (active) {
            // ---- S = Q @ K^T (1 fp16 term) ----
            float s[8][4];
#pragma unroll
            for (int j = 0; j < 8; j++)
#pragma unroll
                for (int c = 0; c < 4; c++) s[j][c] = 0.f;

#pragma unroll
            for (int ks = 0; ks < 8; ks++) {
                uint32_t ah[4];
                ldsm4(ah, aRow + (ks >> 1) * 8192 + ((ks & 1) ? cA1 : cA0));
#pragma unroll
                for (int nb = 0; nb < 4; nb++) {
                    uint32_t kh4[4];
                    ldsm4(kh4, sK + (ks >> 1) * 4096 + nb * 1024 + bRow + ((ks & 1) ? cB1 : cB0));
                    mma_f16(s[nb * 2], ah, kh4);
                    mma_f16(s[nb * 2 + 1], ah, kh4 + 2);
                }
            }

            if (kb >= 2 * qt) {
                int r0 = qt * 128 + warp * 16 + (lane >> 2);
                int c0 = kb * 64 + (lane & 3) * 2;
#pragma unroll
                for (int j = 0; j < 8; j++)
#pragma unroll
                    for (int c = 0; c < 4; c++) {
                        int col = c0 + j * 8 + (c & 1);
                        int row = r0 + ((c & 2) ? 8 : 0);
                        if (col > row) s[j][c] = -1e30f;
                    }
            }

            float mloc[2] = {-1e30f, -1e30f};
#pragma unroll
            for (int j = 0; j < 8; j++) {
                mloc[0] = fmaxf(mloc[0], fmaxf(s[j][0], s[j][1]));
                mloc[1] = fmaxf(mloc[1], fmaxf(s[j][2], s[j][3]));
            }
            float mnew[2], alpha[2], rs[2];
#pragma unroll
            for (int h2 = 0; h2 < 2; h2++) {
                mloc[h2] = fmaxf(mloc[h2], __shfl_xor_sync(0xffffffffu, mloc[h2], 1));
                mloc[h2] = fmaxf(mloc[h2], __shfl_xor_sync(0xffffffffu, mloc[h2], 2));
                mnew[h2] = fmaxf(m_run[h2], mloc[h2]);
                alpha[h2] = exp2f(m_run[h2] - mnew[h2]);
                rs[h2] = 0.f;
            }
#pragma unroll
            for (int j = 0; j < 8; j++) {
                s[j][0] = exp2f(s[j][0] - mnew[0]);
                s[j][1] = exp2f(s[j][1] - mnew[0]);
                s[j][2] = exp2f(s[j][2] - mnew[1]);
                s[j][3] = exp2f(s[j][3] - mnew[1]);
                rs[0] += s[j][0] + s[j][1];
                rs[1] += s[j][2] + s[j][3];
            }
#pragma unroll
            for (int h2 = 0; h2 < 2; h2++) {
                rs[h2] += __shfl_xor_sync(0xffffffffu, rs[h2], 1);
                rs[h2] += __shfl_xor_sync(0xffffffffu, rs[h2], 2);
                l_run[h2] = l_run[h2] * alpha[h2] + rs[h2];
                m_run[h2] = mnew[h2];
            }
#pragma unroll
            for (int j = 0; j < 16; j++) {
                o[j][0] *= alpha[0];
                o[j][1] *= alpha[0];
                o[j][2] *= alpha[1];
                o[j][3] *= alpha[1];
            }

            // ---- O += P @ V (1 fp16 term) ----
#pragma unroll
            for (int kc = 0; kc < 4; kc++) {
                uint32_t pa[4];
                __half2 p0 = __floats2half2_rn(s[2 * kc][0], s[2 * kc][1]);
                __half2 p1 = __floats2half2_rn(s[2 * kc][2], s[2 * kc][3]);
                __half2 p2 = __floats2half2_rn(s[2 * kc + 1][0], s[2 * kc + 1][1]);
                __half2 p3 = __floats2half2_rn(s[2 * kc + 1][2], s[2 * kc + 1][3]);
                pa[0] = *(uint32_t*)&p0;
                pa[1] = *(uint32_t*)&p1;
                pa[2] = *(uint32_t*)&p2;
                pa[3] = *(uint32_t*)&p3;
#pragma unroll
                for (int nb = 0; nb < 8; nb++) {
                    uint32_t vh4[4];
                    ldsm4(vh4, sV + (kc >> 1) * 8192 + nb * 1024 + bRow + ((kc & 1) ? cB1 : cB0));
                    mma_f16(o[nb * 2], pa, vh4);
                    mma_f16(o[nb * 2 + 1], pa, vh4 + 2);
                }
            }
        }

        __syncthreads();
        if (tid == 0 && kb + 2 < nt) ISSUEKV(kb + 2, st);
    }

    // normalize + write fp16 in 256-row tiled-A layout for Wo GEMM
    float inv[2] = {1.f / l_run[0], 1.f / l_run[1]};
    int trow = b * SEQLEN + qt * 128 + warp * 16 + (lane >> 2);
#pragma unroll
    for (int j = 0; j < 16; j++) {
        int c0 = j * 8 + (lane & 3) * 2;
        int k = h * HDIM + c0;
        int ck = k >> 5, c16 = (k & 31) >> 3, bo = (k & 7) * 2;
#pragma unroll
        for (int h2 = 0; h2 < 2; h2++) {
            int t = trow + h2 * 8;
            int mtA = t >> 8, rr = t & 255;
            size_t off = ((((size_t)(mtA * 128 + ck)) * 256 + rr) << 6) +
                         ((c16 ^ ((rr >> 1) & 3)) << 4) + bo;
            __half2 hv = __floats2half2_rn(o[j][h2 * 2] * inv[h2],
                                           o[j][h2 * 2 + 1] * inv[h2]);
            *(uint32_t*)((char*)Oh + off) = *(uint32_t*)&hv;
        }
    }
}

// ---------------------------------------------------------------------------
extern "C" void kernel_launch(void* const* d_in, const int* in_sizes, int n_in,
                              void* d_out, int out_size) {
    const float* x  = (const float*)d_in[0];
    const float* fc = (const float*)d_in[1];
    const float* wq = (const float*)d_in[4];
    const float* wk = (const float*)d_in[5];
    const float* wv = (const float*)d_in[6];
    const float* wo = (const float*)d_in[7];

    float* out = (float*)d_out;
    float* Kh = out + OUT_ELEMS;
    float* Vh = Kh + OUT_ELEMS;

    float* qbuf;
    __half *xh, *wh, *ah, *q16, *k16, *vt16;
    cudaGetSymbolAddress((void**)&qbuf, g_Q);
    cudaGetSymbolAddress((void**)&xh, g_xh);
    cudaGetSymbolAddress((void**)&wh, g_wh);
    cudaGetSymbolAddress((void**)&ah, g_ah);
    cudaGetSymbolAddress((void**)&q16, g_q16);
    cudaGetSymbolAddress((void**)&k16, g_k16);
    cudaGetSymbolAddress((void**)&vt16, g_vt16);

    const int cblocks = (int)(WSZ / 8 / 256);   // 8 elems per thread

    convert_all<<<dim3(cblocks, 5), 256>>>(x, wq, wk, wv, wo, xh, wh);

    cudaFuncSetAttribute(gemm_f16, cudaFuncAttributeMaxDynamicSharedMemorySize, GEMM_SMEM);

    // Fused QKV projection (B tiles 0..95 span wq, wk, wv)
    gemm_f16<<<dim3(96, NTOK / 256), 256, GEMM_SMEM>>>(xh, wh, qbuf, Kh, Vh);

    // Merged rotary (Q,K) + V transpose
    pre_attn<<<ROT_BLOCKS + 16384, 256>>>(qbuf, Kh, fc, Vh, q16, k16, vt16);

    cudaFuncSetAttribute(flash_attn, cudaFuncAttributeMaxDynamicSharedMemorySize, ATTN_SMEM);
    flash_attn<<<dim3(SEQLEN / 128, NHEADS, BSZ), 256, ATTN_SMEM>>>(q16, k16, vt16, ah);

    // Output projection
    gemm_f16<<<dim3(32, NTOK / 256), 256, GEMM_SMEM>>>(ah, wh + 3 * WSZ, out, out, out);
}